// round 1
// baseline (speedup 1.0000x reference)
#include <cuda_runtime.h>
#include <math.h>
#include <float.h>

#define HIDDEN 4096
#define NHEADS 32
#define HDIM   128
#define SEQ    2048
#define SEL    1536           // SEQ - RECENT
#define CACHE  768            // 256 + 512
#define HHK    256

// ---- scratch (device globals: sanctioned, no allocs) ----
__device__ float d_Q[(size_t)SEQ * HIDDEN];
__device__ float d_K[(size_t)SEQ * HIDDEN];
__device__ float d_V[(size_t)SEQ * HIDDEN];
__device__ float d_AO[(size_t)SEQ * HIDDEN];
__device__ float d_P[(size_t)NHEADS * SEQ * SEQ];   // 512 MB attn probs
__device__ float d_HH[NHEADS * SEQ];
__device__ int   d_keep[NHEADS * CACHE];

// ============================================================
// SGEMM NT: C[m,n] = alpha * sum_k A[m,k] * B[n,k]
// BM=BN=128, BK=16, 256 threads, 8x8 per thread.
// grid.z batches with byte-free element strides sAz/sBz/sCz.
// ============================================================
__global__ __launch_bounds__(256) void sgemm_nt(
    const float* __restrict__ A, const float* __restrict__ B, float* __restrict__ C,
    int K, int lda, int ldb, int ldc,
    long long sAz, long long sBz, long long sCz, float alpha)
{
    A += (size_t)blockIdx.z * sAz;
    B += (size_t)blockIdx.z * sBz;
    C += (size_t)blockIdx.z * sCz;
    __shared__ float As[16][132];
    __shared__ float Bs[16][132];
    const int tid = threadIdx.x;
    const int tm = (tid >> 4) << 3;
    const int tn = (tid & 15) << 3;
    const size_t m0 = (size_t)blockIdx.y * 128;
    const size_t n0 = (size_t)blockIdx.x * 128;
    float acc[8][8];
#pragma unroll
    for (int i = 0; i < 8; i++)
#pragma unroll
        for (int j = 0; j < 8; j++) acc[i][j] = 0.f;

    for (int k0 = 0; k0 < K; k0 += 16) {
#pragma unroll
        for (int it = 0; it < 2; it++) {
            int f = tid + it * 256;
            int r = f >> 2;
            int c = (f & 3) << 2;
            float4 a = *(const float4*)(A + (m0 + r) * (size_t)lda + k0 + c);
            As[c][r] = a.x; As[c + 1][r] = a.y; As[c + 2][r] = a.z; As[c + 3][r] = a.w;
            float4 b = *(const float4*)(B + (n0 + r) * (size_t)ldb + k0 + c);
            Bs[c][r] = b.x; Bs[c + 1][r] = b.y; Bs[c + 2][r] = b.z; Bs[c + 3][r] = b.w;
        }
        __syncthreads();
#pragma unroll
        for (int kk = 0; kk < 16; kk++) {
            float ra[8], rb[8];
#pragma unroll
            for (int i = 0; i < 8; i++) { ra[i] = As[kk][tm + i]; rb[i] = Bs[kk][tn + i]; }
#pragma unroll
            for (int i = 0; i < 8; i++)
#pragma unroll
                for (int j = 0; j < 8; j++)
                    acc[i][j] = fmaf(ra[i], rb[j], acc[i][j]);
        }
        __syncthreads();
    }
#pragma unroll
    for (int i = 0; i < 8; i++) {
#pragma unroll
        for (int j = 0; j < 8; j += 4) {
            float4 o;
            o.x = acc[i][j] * alpha; o.y = acc[i][j + 1] * alpha;
            o.z = acc[i][j + 2] * alpha; o.w = acc[i][j + 3] * alpha;
            *(float4*)(C + (m0 + tm + i) * (size_t)ldc + n0 + tn + j) = o;
        }
    }
}

// ============================================================
// SGEMM NN: C[m,n] = sum_k A[m,k] * B[k,n]   (for P @ V)
// ============================================================
__global__ __launch_bounds__(256) void sgemm_nn(
    const float* __restrict__ A, const float* __restrict__ B, float* __restrict__ C,
    int K, int lda, int ldb, int ldc,
    long long sAz, long long sBz, long long sCz)
{
    A += (size_t)blockIdx.z * sAz;
    B += (size_t)blockIdx.z * sBz;
    C += (size_t)blockIdx.z * sCz;
    __shared__ float As[16][132];
    __shared__ float Bs[16][132];
    const int tid = threadIdx.x;
    const int tm = (tid >> 4) << 3;
    const int tn = (tid & 15) << 3;
    const size_t m0 = (size_t)blockIdx.y * 128;
    const size_t n0 = (size_t)blockIdx.x * 128;
    float acc[8][8];
#pragma unroll
    for (int i = 0; i < 8; i++)
#pragma unroll
        for (int j = 0; j < 8; j++) acc[i][j] = 0.f;

    for (int k0 = 0; k0 < K; k0 += 16) {
#pragma unroll
        for (int it = 0; it < 2; it++) {
            int f = tid + it * 256;
            // A tile: 128 rows x 16 cols  (transpose into As)
            int r = f >> 2;
            int c = (f & 3) << 2;
            float4 a = *(const float4*)(A + (m0 + r) * (size_t)lda + k0 + c);
            As[c][r] = a.x; As[c + 1][r] = a.y; As[c + 2][r] = a.z; As[c + 3][r] = a.w;
            // B tile: 16 rows x 128 cols (direct)
            int br = f >> 5;
            int bc = (f & 31) << 2;
            float4 b = *(const float4*)(B + (size_t)(k0 + br) * (size_t)ldb + n0 + bc);
            Bs[br][bc] = b.x; Bs[br][bc + 1] = b.y; Bs[br][bc + 2] = b.z; Bs[br][bc + 3] = b.w;
        }
        __syncthreads();
#pragma unroll
        for (int kk = 0; kk < 16; kk++) {
            float ra[8], rb[8];
#pragma unroll
            for (int i = 0; i < 8; i++) { ra[i] = As[kk][tm + i]; rb[i] = Bs[kk][tn + i]; }
#pragma unroll
            for (int i = 0; i < 8; i++)
#pragma unroll
                for (int j = 0; j < 8; j++)
                    acc[i][j] = fmaf(ra[i], rb[j], acc[i][j]);
        }
        __syncthreads();
    }
#pragma unroll
    for (int i = 0; i < 8; i++) {
#pragma unroll
        for (int j = 0; j < 8; j += 4) {
            float4 o;
            o.x = acc[i][j]; o.y = acc[i][j + 1]; o.z = acc[i][j + 2]; o.w = acc[i][j + 3];
            *(float4*)(C + (m0 + tm + i) * (size_t)ldc + n0 + tn + j) = o;
        }
    }
}

// ============================================================
// RoPE in-place on d_Q, d_K. grid (SEQ, NHEADS), 64 threads.
// ============================================================
__global__ void rope_kernel(const int* __restrict__ pos_ids)
{
    int s = blockIdx.x;
    int h = blockIdx.y;
    int j = threadIdx.x;   // 0..63
    int pos = pos_ids[s];
    float invf = (float)exp(-(double)j * (log(10000.0) / 64.0));
    float ang = (float)pos * invf;
    float c = cosf(ang), si = sinf(ang);
    size_t base = (size_t)s * HIDDEN + (size_t)h * HDIM;
    float q0 = d_Q[base + j], q1 = d_Q[base + 64 + j];
    d_Q[base + j]      = q0 * c - q1 * si;
    d_Q[base + 64 + j] = q1 * c + q0 * si;
    float k0 = d_K[base + j], k1 = d_K[base + 64 + j];
    d_K[base + j]      = k0 * c - k1 * si;
    d_K[base + 64 + j] = k1 * c + k0 * si;
}

// ============================================================
// Causal row softmax in-place on d_P. grid (SEQ, NHEADS), 256 thr.
// Writes exact zeros for k > q (matches exp(x + f32min) == 0).
// ============================================================
__global__ __launch_bounds__(256) void softmax_kernel()
{
    int q = blockIdx.x, h = blockIdx.y;
    float* row = d_P + ((size_t)h * SEQ + q) * SEQ;
    int n = q + 1;
    int tid = threadIdx.x;
    __shared__ float red[256];
    float mx = -FLT_MAX;
    for (int k = tid; k < n; k += 256) mx = fmaxf(mx, row[k]);
    red[tid] = mx; __syncthreads();
    for (int o = 128; o > 0; o >>= 1) { if (tid < o) red[tid] = fmaxf(red[tid], red[tid + o]); __syncthreads(); }
    mx = red[0]; __syncthreads();
    float sum = 0.f;
    for (int k = tid; k < n; k += 256) { float e = expf(row[k] - mx); row[k] = e; sum += e; }
    red[tid] = sum; __syncthreads();
    for (int o = 128; o > 0; o >>= 1) { if (tid < o) red[tid] += red[tid + o]; __syncthreads(); }
    float inv = 1.f / red[0];
    for (int k = tid; k < n; k += 256) row[k] *= inv;
    for (int k = n + tid; k < SEQ; k += 256) row[k] = 0.f;
}

// ============================================================
// hh_score[h,k] = sum_q P[h,q,k]. grid (8, NHEADS), 256 thr.
// ============================================================
__global__ void colsum_kernel()
{
    int h = blockIdx.y;
    int k = blockIdx.x * 256 + threadIdx.x;
    const float* base = d_P + (size_t)h * SEQ * SEQ + k;
    float s0 = 0.f, s1 = 0.f, s2 = 0.f, s3 = 0.f;
    for (int q = 0; q < SEQ; q += 4) {
        s0 += base[(size_t)q * SEQ];
        s1 += base[(size_t)(q + 1) * SEQ];
        s2 += base[(size_t)(q + 2) * SEQ];
        s3 += base[(size_t)(q + 3) * SEQ];
    }
    d_HH[h * SEQ + k] = (s0 + s1) + (s2 + s3);
}

// ============================================================
// Per-head top-256 over hh_score[:,0:1536] (ties -> lower index,
// matching jax.lax.top_k), then sort indices ascending, append
// recent 1536..2047. One block per head, 1024 threads.
// ============================================================
__global__ __launch_bounds__(1024) void topk_kernel()
{
    __shared__ float sv[2048];
    __shared__ int   si[2048];
    __shared__ int   tki[256];
    int h = blockIdx.x, tid = threadIdx.x;
    for (int i = tid; i < 2048; i += 1024) {
        sv[i] = (i < SEL) ? d_HH[h * SEQ + i] : -FLT_MAX;
        si[i] = i;
    }
    __syncthreads();
    // bitonic sort, descending by value, ascending idx on ties
    for (int k = 2; k <= 2048; k <<= 1) {
        for (int j = k >> 1; j > 0; j >>= 1) {
            for (int i = tid; i < 2048; i += 1024) {
                int l = i ^ j;
                if (l > i) {
                    float vi = sv[i], vl = sv[l];
                    int ii = si[i], il = si[l];
                    bool up = ((i & k) == 0);
                    bool bli = (vl > vi) || (vl == vi && il < ii);  // l precedes i
                    bool bil = (vi > vl) || (vi == vl && ii < il);  // i precedes l
                    if (up ? bli : bil) {
                        sv[i] = vl; sv[l] = vi; si[i] = il; si[l] = ii;
                    }
                }
            }
            __syncthreads();
        }
    }
    if (tid < 256) tki[tid] = si[tid];
    __syncthreads();
    // sort the 256 kept indices ascending
    for (int k = 2; k <= 256; k <<= 1) {
        for (int j = k >> 1; j > 0; j >>= 1) {
            if (tid < 256) {
                int i = tid, l = i ^ j;
                if (l > i) {
                    int a = tki[i], b = tki[l];
                    bool up = ((i & k) == 0);
                    if (up ? (a > b) : (a < b)) { tki[i] = b; tki[l] = a; }
                }
            }
            __syncthreads();
        }
    }
    for (int i = tid; i < CACHE; i += 1024)
        d_keep[h * CACHE + i] = (i < HHK) ? tki[i] : (SEL + (i - HHK));
}

// ============================================================
// Gather k_hh, v_hh, hh_score_kept into d_out.
// d_out layout: out[8388608] | k_hh[3145728] | v_hh[3145728] | hh[24576]
// ============================================================
__global__ void gather_kernel(float* __restrict__ out)
{
    int h = blockIdx.y, j = blockIdx.x, d = threadIdx.x;
    int s = d_keep[h * CACHE + j];
    size_t dst = (size_t)8388608 + ((size_t)h * CACHE + j) * HDIM + d;
    size_t src = (size_t)s * HIDDEN + (size_t)h * HDIM + d;
    out[dst] = d_K[src];
    out[dst + 3145728] = d_V[src];
    if (d == 0) out[(size_t)14680064 + h * CACHE + j] = d_HH[h * SEQ + s];
}

extern "C" void kernel_launch(void* const* d_in, const int* in_sizes, int n_in,
                              void* d_out, int out_size)
{
    const float* hs = (const float*)d_in[0];
    const int*   pos = (const int*)d_in[1];
    const float* Wq = (const float*)d_in[2];
    const float* Wk = (const float*)d_in[3];
    const float* Wv = (const float*)d_in[4];
    const float* Wo = (const float*)d_in[5];
    float* out = (float*)d_out;

    float *Qp, *Kp, *Vp, *AOp, *Pp;
    cudaGetSymbolAddress((void**)&Qp, d_Q);
    cudaGetSymbolAddress((void**)&Kp, d_K);
    cudaGetSymbolAddress((void**)&Vp, d_V);
    cudaGetSymbolAddress((void**)&AOp, d_AO);
    cudaGetSymbolAddress((void**)&Pp, d_P);

    const float inv_sqrt_d = 1.0f / sqrtf((float)HDIM);

    // Q, K, V projections: [2048,4096] = HS[2048,4096] @ W^T
    sgemm_nt<<<dim3(32, 16, 1), 256>>>(hs, Wq, Qp, HIDDEN, HIDDEN, HIDDEN, HIDDEN, 0, 0, 0, 1.f);
    sgemm_nt<<<dim3(32, 16, 1), 256>>>(hs, Wk, Kp, HIDDEN, HIDDEN, HIDDEN, HIDDEN, 0, 0, 0, 1.f);
    sgemm_nt<<<dim3(32, 16, 1), 256>>>(hs, Wv, Vp, HIDDEN, HIDDEN, HIDDEN, HIDDEN, 0, 0, 0, 1.f);

    rope_kernel<<<dim3(SEQ, NHEADS), 64>>>(pos);

    // scores: per head, P[h] = (Q_h @ K_h^T) / sqrt(d)
    sgemm_nt<<<dim3(16, 16, NHEADS), 256>>>(Qp, Kp, Pp, HDIM, HIDDEN, HIDDEN, SEQ,
                                            HDIM, HDIM, (long long)SEQ * SEQ, inv_sqrt_d);

    softmax_kernel<<<dim3(SEQ, NHEADS), 256>>>();
    colsum_kernel<<<dim3(8, NHEADS), 256>>>();

    // AO_h = P[h] @ V_h  (NN form)
    sgemm_nn<<<dim3(1, 16, NHEADS), 256>>>(Pp, Vp, AOp, SEQ, SEQ, HIDDEN, HIDDEN,
                                           (long long)SEQ * SEQ, HDIM, HDIM);

    // out = AO @ Wo^T  (written straight into d_out)
    sgemm_nt<<<dim3(32, 16, 1), 256>>>(AOp, Wo, out, HIDDEN, HIDDEN, HIDDEN, HIDDEN, 0, 0, 0, 1.f);

    topk_kernel<<<NHEADS, 1024>>>();
    gather_kernel<<<dim3(CACHE, NHEADS), 128>>>(out);
}

// round 3
// speedup vs baseline: 1.9398x; 1.9398x over previous
#include <cuda_runtime.h>
#include <cuda_fp16.h>
#include <math.h>
#include <float.h>
#include <stdint.h>

#define HIDDEN 4096
#define NHEADS 32
#define HDIM   128
#define SEQ    2048
#define SEL    1536
#define CACHE  768
#define HHK    256

typedef __half  h16;
typedef __half2 h162;

// ---------------- device scratch ----------------
__device__ float d_Q[(size_t)SEQ * HIDDEN];
__device__ float d_K[(size_t)SEQ * HIDDEN];
__device__ float d_V[(size_t)SEQ * HIDDEN];
__device__ float d_AO[(size_t)SEQ * HIDDEN];
__device__ float d_S[(size_t)NHEADS * SEQ * SEQ];       // attention scores fp32
__device__ h16   d_HSh[(size_t)SEQ * HIDDEN], d_HSl[(size_t)SEQ * HIDDEN];
__device__ h16   d_Wh[4][(size_t)HIDDEN * HIDDEN];
__device__ h16   d_Wl[4][(size_t)HIDDEN * HIDDEN];
__device__ h16   d_Qh[(size_t)SEQ * HIDDEN], d_Ql[(size_t)SEQ * HIDDEN];
__device__ h16   d_Kh[(size_t)SEQ * HIDDEN], d_Kl[(size_t)SEQ * HIDDEN];
__device__ h16   d_Vth[(size_t)HIDDEN * SEQ], d_Vtl[(size_t)HIDDEN * SEQ]; // per-head [d][s]
__device__ h16   d_Ph[(size_t)NHEADS * SEQ * SEQ], d_Pl[(size_t)NHEADS * SEQ * SEQ];
__device__ h16   d_AOh[(size_t)SEQ * HIDDEN], d_AOl[(size_t)SEQ * HIDDEN];
__device__ float d_HH[NHEADS * SEQ];
__device__ int   d_keep[NHEADS * CACHE];
__device__ float d_invf[64];

// ---------------- helpers ----------------
__device__ __forceinline__ uint32_t smem_u32(const void* p) {
    uint32_t a;
    asm("{ .reg .u64 t; cvta.to.shared.u64 t, %1; cvt.u32.u64 %0, t; }" : "=r"(a) : "l"(p));
    return a;
}
__device__ __forceinline__ uint32_t sw64(uint32_t off) { return off ^ ((off >> 3) & 0x30); }

#define LDSM4(R, A) \
    asm volatile("ldmatrix.sync.aligned.m8n8.x4.shared.b16 {%0,%1,%2,%3}, [%4];" \
                 : "=r"((R)[0]), "=r"((R)[1]), "=r"((R)[2]), "=r"((R)[3]) : "r"(A))

#define MMA16816(C, A, B) \
    asm volatile("mma.sync.aligned.m16n8k16.row.col.f32.f16.f16.f32 " \
                 "{%0,%1,%2,%3},{%4,%5,%6,%7},{%8,%9},{%0,%1,%2,%3};" \
                 : "+f"((C)[0]), "+f"((C)[1]), "+f"((C)[2]), "+f"((C)[3]) \
                 : "r"((A)[0]), "r"((A)[1]), "r"((A)[2]), "r"((A)[3]), \
                   "r"((B)[0]), "r"((B)[1]))

#define CP16(DST, SRC) \
    asm volatile("cp.async.cg.shared.global [%0], [%1], 16;" :: "r"(DST), "l"(SRC) : "memory")
#define CP_COMMIT() asm volatile("cp.async.commit_group;" ::: "memory")
#define CP_WAIT1()  asm volatile("cp.async.wait_group 1;" ::: "memory")

// ============================================================
// Split-fp16 HMMA GEMM:  C[m,n] = alpha * sum_k A[m,k]*B[n,k]
// A=Ahi+Alo, B=Bhi+Blo (fp16, K-major). CTA 128x128, BK=32.
// 8 warps (2x4), warptile 64x32 of m16n8k16.
// mode: 0 normal, 1 causal-skip n0>m0, 2 causal K-limit (PV)
// ============================================================
#define BM 128
#define BN 128
#define BK 32
#define TILEB 8192            // one operand tile: 128*32 halfs
#define STGB  (4 * TILEB)     // 32 KB/stage
#define GSMEM (2 * STGB)      // 64 KB

__global__ __launch_bounds__(256) void gemm_hsplit(
    const h16* __restrict__ Ahi, const h16* __restrict__ Alo,
    const h16* __restrict__ Bhi, const h16* __restrict__ Blo,
    float* __restrict__ C,
    int K, int lda, int ldb, int ldc,
    long long sAz, long long sBz, long long sCz,
    float alpha, int mode)
{
    const int m0 = blockIdx.y * BM;
    const int n0 = blockIdx.x * BN;
    if (mode == 1 && n0 > m0) return;
    Ahi += (size_t)blockIdx.z * sAz; Alo += (size_t)blockIdx.z * sAz;
    Bhi += (size_t)blockIdx.z * sBz; Blo += (size_t)blockIdx.z * sBz;
    C   += (size_t)blockIdx.z * sCz;

    extern __shared__ char smem[];
    const uint32_t sb = smem_u32(smem);
    const int tid = threadIdx.x;
    const int lane = tid & 31;
    const int wid = tid >> 5;
    const int wm = (wid >> 2) * 64;       // warp m offset (0 / 64)
    const int wn = (wid & 3) * 32;        // warp n offset (0/32/64/96)

    int nch = K / BK;
    if (mode == 2) { int lim = (m0 >> 5) + 4; if (lim < nch) nch = lim; }

    const h16* pAh = Ahi + (size_t)m0 * lda;
    const h16* pAl = Alo + (size_t)m0 * lda;
    const h16* pBh = Bhi + (size_t)n0 * ldb;
    const h16* pBl = Blo + (size_t)n0 * ldb;

#define LOAD_STAGE(I)                                                        \
    {                                                                        \
        const int k0_ = (I) * BK;                                            \
        const uint32_t base_ = sb + ((I) & 1) * STGB;                        \
        _Pragma("unroll")                                                    \
        for (int hh = 0; hh < 2; hh++) {                                     \
            int idx = tid + hh * 256;                                        \
            int row = idx >> 2, ch = idx & 3;                                \
            uint32_t so = sw64((uint32_t)(row * 64 + ch * 16));              \
            CP16(base_ + 0 * TILEB + so, pAh + (size_t)row * lda + k0_ + ch * 8); \
            CP16(base_ + 1 * TILEB + so, pAl + (size_t)row * lda + k0_ + ch * 8); \
            CP16(base_ + 2 * TILEB + so, pBh + (size_t)row * ldb + k0_ + ch * 8); \
            CP16(base_ + 3 * TILEB + so, pBl + (size_t)row * ldb + k0_ + ch * 8); \
        }                                                                    \
        CP_COMMIT();                                                         \
    }

    float acc[4][4][4];
#pragma unroll
    for (int i = 0; i < 4; i++)
#pragma unroll
        for (int j = 0; j < 4; j++)
#pragma unroll
            for (int e = 0; e < 4; e++) acc[i][j][e] = 0.f;

    LOAD_STAGE(0)
    LOAD_STAGE(1)

    // per-lane ldmatrix row/chunk components
    const int rA = wm + (lane & 15);            // A row within CTA tile
    const int cA = lane >> 4;                   // extra k-chunk bit
    const int rB = wn + ((lane >> 4) & 1) * 8 + (lane & 7);
    const int cB = (lane >> 3) & 1;

    for (int it = 0; it < nch; it++) {
        CP_WAIT1();
        __syncthreads();
        const uint32_t base = sb + (it & 1) * STGB;
        const uint32_t aHiB = base, aLoB = base + TILEB;
        const uint32_t bHiB = base + 2 * TILEB, bLoB = base + 3 * TILEB;
#pragma unroll
        for (int ks = 0; ks < 2; ks++) {
            uint32_t ah[4][4], al[4][4], bh[4][2], bl[4][2];
            const int chA = ks * 2 + cA;
#pragma unroll
            for (int i = 0; i < 4; i++) {
                uint32_t off = sw64((uint32_t)((rA + i * 16) * 64 + chA * 16));
                LDSM4(ah[i], aHiB + off);
                LDSM4(al[i], aLoB + off);
            }
            const int chB = ks * 2 + cB;
#pragma unroll
            for (int p = 0; p < 2; p++) {
                uint32_t off = sw64((uint32_t)((rB + p * 16) * 64 + chB * 16));
                uint32_t r[4];
                LDSM4(r, bHiB + off);
                bh[2 * p][0] = r[0]; bh[2 * p][1] = r[1];
                bh[2 * p + 1][0] = r[2]; bh[2 * p + 1][1] = r[3];
                LDSM4(r, bLoB + off);
                bl[2 * p][0] = r[0]; bl[2 * p][1] = r[1];
                bl[2 * p + 1][0] = r[2]; bl[2 * p + 1][1] = r[3];
            }
#pragma unroll
            for (int i = 0; i < 4; i++)
#pragma unroll
                for (int j = 0; j < 4; j++) {
                    MMA16816(acc[i][j], ah[i], bh[j]);
                    MMA16816(acc[i][j], ah[i], bl[j]);
                    MMA16816(acc[i][j], al[i], bh[j]);
                }
        }
        __syncthreads();
        if (it + 2 < nch) { LOAD_STAGE(it + 2) } else { CP_COMMIT(); }
    }
#undef LOAD_STAGE

    // epilogue
    const int gr = lane >> 2;
    const int gc = (lane & 3) * 2;
#pragma unroll
    for (int i = 0; i < 4; i++) {
#pragma unroll
        for (int j = 0; j < 4; j++) {
            int row = m0 + wm + i * 16 + gr;
            int col = n0 + wn + j * 8 + gc;
            float2 v0 = { acc[i][j][0] * alpha, acc[i][j][1] * alpha };
            float2 v1 = { acc[i][j][2] * alpha, acc[i][j][3] * alpha };
            *(float2*)(C + (size_t)row * ldc + col) = v0;
            *(float2*)(C + (size_t)(row + 8) * ldc + col) = v1;
        }
    }
}

// ============================================================
// elementwise: fp32 -> fp16 hi/lo split
// ============================================================
__global__ void split_kernel(const float* __restrict__ src, h16* __restrict__ hi,
                             h16* __restrict__ lo, int n4)
{
    int i = blockIdx.x * blockDim.x + threadIdx.x;
    if (i >= n4) return;
    float4 v = ((const float4*)src)[i];
    h16 h0 = __float2half_rn(v.x), h1 = __float2half_rn(v.y);
    h16 h2 = __float2half_rn(v.z), h3 = __float2half_rn(v.w);
    h162 H0; H0.x = h0; H0.y = h1;
    h162 H1; H1.x = h2; H1.y = h3;
    ((h162*)hi)[2 * i] = H0; ((h162*)hi)[2 * i + 1] = H1;
    h162 L0, L1;
    L0.x = __float2half_rn(v.x - __half2float(h0));
    L0.y = __float2half_rn(v.y - __half2float(h1));
    L1.x = __float2half_rn(v.z - __half2float(h2));
    L1.y = __float2half_rn(v.w - __half2float(h3));
    ((h162*)lo)[2 * i] = L0; ((h162*)lo)[2 * i + 1] = L1;
}

__global__ void invf_kernel()
{
    int j = threadIdx.x;   // 64
    d_invf[j] = (float)exp(-(double)j * (log(10000.0) / 64.0));
}

// ============================================================
// RoPE on Q,K (fp32 in-place) + fused hi/lo split. grid(SEQ), 512 thr.
// ============================================================
__device__ __forceinline__ void st_hl(h16* hi, h16* lo, size_t idx, float a, float b)
{
    h162 H; H.x = __float2half_rn(a); H.y = __float2half_rn(b);
    *(h162*)(hi + idx) = H;
    h162 L;
    L.x = __float2half_rn(a - __half2float(H.x));
    L.y = __float2half_rn(b - __half2float(H.y));
    *(h162*)(lo + idx) = L;
}

__global__ __launch_bounds__(512) void rope_split_kernel(const int* __restrict__ pos_ids)
{
    int s = blockIdx.x;
    int t = threadIdx.x;
    int h = t >> 4;
    int j = (t & 15) << 2;
    float pos = (float)pos_ids[s];
    size_t base = (size_t)s * HIDDEN + (size_t)h * HDIM;
    float4 q0 = *(float4*)(d_Q + base + j);
    float4 q1 = *(float4*)(d_Q + base + 64 + j);
    float4 k0 = *(float4*)(d_K + base + j);
    float4 k1 = *(float4*)(d_K + base + 64 + j);
    float cc[4], ss[4];
#pragma unroll
    for (int e = 0; e < 4; e++) {
        float ang = pos * d_invf[j + e];
        sincosf(ang, &ss[e], &cc[e]);
    }
    float4 Q0, Q1, K0, K1;
    Q0.x = q0.x * cc[0] - q1.x * ss[0];  Q1.x = q1.x * cc[0] + q0.x * ss[0];
    Q0.y = q0.y * cc[1] - q1.y * ss[1];  Q1.y = q1.y * cc[1] + q0.y * ss[1];
    Q0.z = q0.z * cc[2] - q1.z * ss[2];  Q1.z = q1.z * cc[2] + q0.z * ss[2];
    Q0.w = q0.w * cc[3] - q1.w * ss[3];  Q1.w = q1.w * cc[3] + q0.w * ss[3];
    K0.x = k0.x * cc[0] - k1.x * ss[0];  K1.x = k1.x * cc[0] + k0.x * ss[0];
    K0.y = k0.y * cc[1] - k1.y * ss[1];  K1.y = k1.y * cc[1] + k0.y * ss[1];
    K0.z = k0.z * cc[2] - k1.z * ss[2];  K1.z = k1.z * cc[2] + k0.z * ss[2];
    K0.w = k0.w * cc[3] - k1.w * ss[3];  K1.w = k1.w * cc[3] + k0.w * ss[3];
    *(float4*)(d_Q + base + j) = Q0;      *(float4*)(d_Q + base + 64 + j) = Q1;
    *(float4*)(d_K + base + j) = K0;      *(float4*)(d_K + base + 64 + j) = K1;
    st_hl(d_Qh, d_Ql, base + j, Q0.x, Q0.y);       st_hl(d_Qh, d_Ql, base + j + 2, Q0.z, Q0.w);
    st_hl(d_Qh, d_Ql, base + 64 + j, Q1.x, Q1.y);  st_hl(d_Qh, d_Ql, base + 64 + j + 2, Q1.z, Q1.w);
    st_hl(d_Kh, d_Kl, base + j, K0.x, K0.y);       st_hl(d_Kh, d_Kl, base + j + 2, K0.z, K0.w);
    st_hl(d_Kh, d_Kl, base + 64 + j, K1.x, K1.y);  st_hl(d_Kh, d_Kl, base + 64 + j + 2, K1.z, K1.w);
}

// ============================================================
// V transpose + split: Vt[h][d][s] = V[s][h*128+d]. grid(64,4,32), block(32,8)
// ============================================================
__global__ void vtrans_kernel()
{
    __shared__ float tile[32][33];
    int h = blockIdx.z;
    int s0 = blockIdx.x * 32;
    int d0 = blockIdx.y * 32;
    for (int r = threadIdx.y; r < 32; r += 8)
        tile[r][threadIdx.x] = d_V[(size_t)(s0 + r) * HIDDEN + h * HDIM + d0 + threadIdx.x];
    __syncthreads();
    for (int r = threadIdx.y; r < 32; r += 8) {
        float x = tile[threadIdx.x][r];
        size_t idx = ((size_t)h * HDIM + d0 + r) * SEQ + s0 + threadIdx.x;
        h16 hi = __float2half_rn(x);
        d_Vth[idx] = hi;
        d_Vtl[idx] = __float2half_rn(x - __half2float(hi));
    }
}

// ============================================================
// causal softmax: read d_S row, write P as fp16 hi/lo. grid(SEQ, NHEADS)
// ============================================================
__global__ __launch_bounds__(256) void softmax_kernel()
{
    __shared__ float red[256];
    __shared__ float ebuf[SEQ];
    int q = blockIdx.x, h = blockIdx.y;
    const float* srow = d_S + ((size_t)h * SEQ + q) * SEQ;
    h16* ph = d_Ph + ((size_t)h * SEQ + q) * SEQ;
    h16* pl = d_Pl + ((size_t)h * SEQ + q) * SEQ;
    int n = q + 1;
    int tid = threadIdx.x;
    float mx = -FLT_MAX;
    for (int k = tid; k < n; k += 256) mx = fmaxf(mx, srow[k]);
    red[tid] = mx; __syncthreads();
    for (int o = 128; o > 0; o >>= 1) { if (tid < o) red[tid] = fmaxf(red[tid], red[tid + o]); __syncthreads(); }
    mx = red[0]; __syncthreads();
    float sum = 0.f;
    for (int k = tid; k < n; k += 256) { float e = expf(srow[k] - mx); ebuf[k] = e; sum += e; }
    red[tid] = sum; __syncthreads();
    for (int o = 128; o > 0; o >>= 1) { if (tid < o) red[tid] += red[tid + o]; __syncthreads(); }
    float inv = 1.f / red[0];
    for (int k = tid; k < n; k += 256) {
        float p = ebuf[k] * inv;
        h16 hi = __float2half_rn(p);
        ph[k] = hi;
        pl[k] = __float2half_rn(p - __half2float(hi));
    }
    h16 z = __float2half_rn(0.f);
    for (int k = n + tid; k < SEQ; k += 256) { ph[k] = z; pl[k] = z; }
}

// ============================================================
// hh_score[h,k] = sum_q P[h,q,k] (hi+lo). grid(8, NHEADS), 256 thr.
// ============================================================
__global__ void colsum_kernel()
{
    int h = blockIdx.y;
    int k = blockIdx.x * 256 + threadIdx.x;
    int qs = blockIdx.x * 256;              // P[q][k]=0 for q<k
    const h16* bh = d_Ph + (size_t)h * SEQ * SEQ + k;
    const h16* bl = d_Pl + (size_t)h * SEQ * SEQ + k;
    float s0 = 0.f, s1 = 0.f, s2 = 0.f, s3 = 0.f;
    for (int q = qs; q < SEQ; q += 4) {
        s0 += __half2float(bh[(size_t)q * SEQ]) + __half2float(bl[(size_t)q * SEQ]);
        s1 += __half2float(bh[(size_t)(q + 1) * SEQ]) + __half2float(bl[(size_t)(q + 1) * SEQ]);
        s2 += __half2float(bh[(size_t)(q + 2) * SEQ]) + __half2float(bl[(size_t)(q + 2) * SEQ]);
        s3 += __half2float(bh[(size_t)(q + 3) * SEQ]) + __half2float(bl[(size_t)(q + 3) * SEQ]);
    }
    d_HH[h * SEQ + k] = (s0 + s1) + (s2 + s3);
}

// ============================================================
// top-256 per head + sort
// ============================================================
__global__ __launch_bounds__(1024) void topk_kernel()
{
    __shared__ float sv[2048];
    __shared__ int   si[2048];
    __shared__ int   tki[256];
    int h = blockIdx.x, tid = threadIdx.x;
    for (int i = tid; i < 2048; i += 1024) {
        sv[i] = (i < SEL) ? d_HH[h * SEQ + i] : -FLT_MAX;
        si[i] = i;
    }
    __syncthreads();
    for (int k = 2; k <= 2048; k <<= 1) {
        for (int j = k >> 1; j > 0; j >>= 1) {
            for (int i = tid; i < 2048; i += 1024) {
                int l = i ^ j;
                if (l > i) {
                    float vi = sv[i], vl = sv[l];
                    int ii = si[i], il = si[l];
                    bool up = ((i & k) == 0);
                    bool bli = (vl > vi) || (vl == vi && il < ii);
                    bool bil = (vi > vl) || (vi == vl && ii < il);
                    if (up ? bli : bil) { sv[i] = vl; sv[l] = vi; si[i] = il; si[l] = ii; }
                }
            }
            __syncthreads();
        }
    }
    if (tid < 256) tki[tid] = si[tid];
    __syncthreads();
    for (int k = 2; k <= 256; k <<= 1) {
        for (int j = k >> 1; j > 0; j >>= 1) {
            if (tid < 256) {
                int i = tid, l = i ^ j;
                if (l > i) {
                    int a = tki[i], b = tki[l];
                    bool up = ((i & k) == 0);
                    if (up ? (a > b) : (a < b)) { tki[i] = b; tki[l] = a; }
                }
            }
            __syncthreads();
        }
    }
    for (int i = tid; i < CACHE; i += 1024)
        d_keep[h * CACHE + i] = (i < HHK) ? tki[i] : (SEL + (i - HHK));
}

__global__ void gather_kernel(float* __restrict__ out)
{
    int h = blockIdx.y, j = blockIdx.x, d = threadIdx.x;
    int s = d_keep[h * CACHE + j];
    size_t dst = (size_t)8388608 + ((size_t)h * CACHE + j) * HDIM + d;
    size_t src = (size_t)s * HIDDEN + (size_t)h * HDIM + d;
    out[dst] = d_K[src];
    out[dst + 3145728] = d_V[src];
    if (d == 0) out[(size_t)14680064 + h * CACHE + j] = d_HH[h * SEQ + s];
}

// ============================================================
extern "C" void kernel_launch(void* const* d_in, const int* in_sizes, int n_in,
                              void* d_out, int out_size)
{
    const float* hs  = (const float*)d_in[0];
    const int*   pos = (const int*)d_in[1];
    const float* W[4] = { (const float*)d_in[2], (const float*)d_in[3],
                          (const float*)d_in[4], (const float*)d_in[5] };
    float* out = (float*)d_out;

    cudaFuncSetAttribute(gemm_hsplit, cudaFuncAttributeMaxDynamicSharedMemorySize, GSMEM);

    float *Qp, *Kp, *Vp, *AOp, *Sp;
    h16 *HSh, *HSl, *Whp[4], *Wlp[4], *Qhp, *Qlp, *Khp, *Klp, *Vthp, *Vtlp, *Php, *Plp, *AOhp, *AOlp;
    cudaGetSymbolAddress((void**)&Qp, d_Q);   cudaGetSymbolAddress((void**)&Kp, d_K);
    cudaGetSymbolAddress((void**)&Vp, d_V);   cudaGetSymbolAddress((void**)&AOp, d_AO);
    cudaGetSymbolAddress((void**)&Sp, d_S);
    cudaGetSymbolAddress((void**)&HSh, d_HSh); cudaGetSymbolAddress((void**)&HSl, d_HSl);
    {
        h16 *wh, *wl;
        cudaGetSymbolAddress((void**)&wh, d_Wh); cudaGetSymbolAddress((void**)&wl, d_Wl);
        for (int i = 0; i < 4; i++) { Whp[i] = wh + (size_t)i * HIDDEN * HIDDEN; Wlp[i] = wl + (size_t)i * HIDDEN * HIDDEN; }
    }
    cudaGetSymbolAddress((void**)&Qhp, d_Qh); cudaGetSymbolAddress((void**)&Qlp, d_Ql);
    cudaGetSymbolAddress((void**)&Khp, d_Kh); cudaGetSymbolAddress((void**)&Klp, d_Kl);
    cudaGetSymbolAddress((void**)&Vthp, d_Vth); cudaGetSymbolAddress((void**)&Vtlp, d_Vtl);
    cudaGetSymbolAddress((void**)&Php, d_Ph); cudaGetSymbolAddress((void**)&Plp, d_Pl);
    cudaGetSymbolAddress((void**)&AOhp, d_AOh); cudaGetSymbolAddress((void**)&AOlp, d_AOl);

    const float inv_sqrt_d = 0.08838834764831843f;

    invf_kernel<<<1, 64>>>();

    split_kernel<<<(SEQ * HIDDEN / 4 + 255) / 256, 256>>>(hs, HSh, HSl, SEQ * HIDDEN / 4);
    for (int i = 0; i < 4; i++)
        split_kernel<<<(HIDDEN * HIDDEN / 4 + 255) / 256, 256>>>(W[i], Whp[i], Wlp[i], HIDDEN * HIDDEN / 4);

    // projections: [2048,4096] = HS @ W^T
    gemm_hsplit<<<dim3(32, 16, 1), 256, GSMEM>>>(HSh, HSl, Whp[0], Wlp[0], Qp,
        HIDDEN, HIDDEN, HIDDEN, HIDDEN, 0, 0, 0, 1.f, 0);
    gemm_hsplit<<<dim3(32, 16, 1), 256, GSMEM>>>(HSh, HSl, Whp[1], Wlp[1], Kp,
        HIDDEN, HIDDEN, HIDDEN, HIDDEN, 0, 0, 0, 1.f, 0);
    gemm_hsplit<<<dim3(32, 16, 1), 256, GSMEM>>>(HSh, HSl, Whp[2], Wlp[2], Vp,
        HIDDEN, HIDDEN, HIDDEN, HIDDEN, 0, 0, 0, 1.f, 0);

    rope_split_kernel<<<SEQ, 512>>>(pos);
    vtrans_kernel<<<dim3(SEQ / 32, HDIM / 32, NHEADS), dim3(32, 8)>>>();

    // scores: S[h] = (Q_h @ K_h^T)/sqrt(d)   (causal tile skip)
    gemm_hsplit<<<dim3(16, 16, NHEADS), 256, GSMEM>>>(Qhp, Qlp, Khp, Klp, Sp,
        HDIM, HIDDEN, HIDDEN, SEQ, HDIM, HDIM, (long long)SEQ * SEQ, inv_sqrt_d, 1);

    softmax_kernel<<<dim3(SEQ, NHEADS), 256>>>();
    colsum_kernel<<<dim3(8, NHEADS), 256>>>();

    // AO_h = P[h] @ V_h   (B = Vt per head, causal K limit)
    gemm_hsplit<<<dim3(1, 16, NHEADS), 256, GSMEM>>>(Php, Plp, Vthp, Vtlp, AOp,
        SEQ, SEQ, SEQ, HIDDEN, (long long)SEQ * SEQ, (long long)HDIM * SEQ, HDIM, 1.f, 2);

    split_kernel<<<(SEQ * HIDDEN / 4 + 255) / 256, 256>>>(AOp, AOhp, AOlp, SEQ * HIDDEN / 4);

    // out = AO @ Wo^T
    gemm_hsplit<<<dim3(32, 16, 1), 256, GSMEM>>>(AOhp, AOlp, Whp[3], Wlp[3], out,
        HIDDEN, HIDDEN, HIDDEN, HIDDEN, 0, 0, 0, 1.f, 0);

    topk_kernel<<<NHEADS, 1024>>>();
    gather_kernel<<<dim3(CACHE, NHEADS), 128>>>(out);
}

// round 4
// speedup vs baseline: 2.3303x; 1.2013x over previous
#include <cuda_runtime.h>
#include <cuda_fp16.h>
#include <math.h>
#include <float.h>
#include <stdint.h>

#define HIDDEN 4096
#define NHEADS 32
#define HDIM   128
#define SEQ    2048
#define SEL    1536
#define CACHE  768
#define HHK    256

typedef __half  h16;
typedef __half2 h162;

// ---------------- device scratch ----------------
__device__ float d_Q[(size_t)SEQ * HIDDEN];
__device__ float d_K[(size_t)SEQ * HIDDEN];
__device__ float d_V[(size_t)SEQ * HIDDEN];
__device__ float d_AO[(size_t)SEQ * HIDDEN];
__device__ float d_S[(size_t)NHEADS * SEQ * SEQ];       // attention scores fp32
__device__ h16   d_HSh[(size_t)SEQ * HIDDEN], d_HSl[(size_t)SEQ * HIDDEN];
__device__ h16   d_Wh[4][(size_t)HIDDEN * HIDDEN];
__device__ h16   d_Wl[4][(size_t)HIDDEN * HIDDEN];
__device__ h16   d_Qh[(size_t)SEQ * HIDDEN], d_Ql[(size_t)SEQ * HIDDEN];
__device__ h16   d_Kh[(size_t)SEQ * HIDDEN], d_Kl[(size_t)SEQ * HIDDEN];
__device__ h16   d_Vth[(size_t)HIDDEN * SEQ], d_Vtl[(size_t)HIDDEN * SEQ]; // per-head [d][s]
__device__ h16   d_Ph[(size_t)NHEADS * SEQ * SEQ], d_Pl[(size_t)NHEADS * SEQ * SEQ];
__device__ h16   d_AOh[(size_t)SEQ * HIDDEN], d_AOl[(size_t)SEQ * HIDDEN];
__device__ float d_HH[NHEADS * SEQ];
__device__ int   d_keep[NHEADS * CACHE];
__device__ float d_invf[64];

// ---------------- helpers ----------------
__device__ __forceinline__ uint32_t smem_u32(const void* p) {
    uint32_t a;
    asm("{ .reg .u64 t; cvta.to.shared.u64 t, %1; cvt.u32.u64 %0, t; }" : "=r"(a) : "l"(p));
    return a;
}
__device__ __forceinline__ uint32_t sw64(uint32_t off) { return off ^ ((off >> 3) & 0x30); }

#define LDSM4(R, A) \
    asm volatile("ldmatrix.sync.aligned.m8n8.x4.shared.b16 {%0,%1,%2,%3}, [%4];" \
                 : "=r"((R)[0]), "=r"((R)[1]), "=r"((R)[2]), "=r"((R)[3]) : "r"(A))

#define MMA16816(C, A, B) \
    asm volatile("mma.sync.aligned.m16n8k16.row.col.f32.f16.f16.f32 " \
                 "{%0,%1,%2,%3},{%4,%5,%6,%7},{%8,%9},{%0,%1,%2,%3};" \
                 : "+f"((C)[0]), "+f"((C)[1]), "+f"((C)[2]), "+f"((C)[3]) \
                 : "r"((A)[0]), "r"((A)[1]), "r"((A)[2]), "r"((A)[3]), \
                   "r"((B)[0]), "r"((B)[1]))

#define CP16(DST, SRC) \
    asm volatile("cp.async.cg.shared.global [%0], [%1], 16;" :: "r"(DST), "l"(SRC) : "memory")
#define CP_COMMIT() asm volatile("cp.async.commit_group;" ::: "memory")
#define CP_WAIT1()  asm volatile("cp.async.wait_group 1;" ::: "memory")

// ============================================================
// Split-fp16 HMMA GEMM:  C[m,n] = alpha * sum_k A[m,k]*B[n,k]
// A=Ahi+Alo, B=Bhi+Blo (fp16, K-major). CTA 128x128, BK=32.
// 8 warps (2x4), warptile 64x32 of m16n8k16.
// mode: 0 normal, 1 causal-skip n0>m0, 2 causal K-limit (PV)
// drop: 0 = 3-term, 1 = drop B-lo term, 2 = drop A-lo term
// ============================================================
#define BM 128
#define BN 128
#define BK 32
#define TILEB 8192            // one operand tile: 128*32 halfs
#define STGB  (4 * TILEB)     // 32 KB/stage
#define GSMEM (2 * STGB)      // 64 KB

__global__ __launch_bounds__(256) void gemm_hsplit(
    const h16* __restrict__ Ahi, const h16* __restrict__ Alo,
    const h16* __restrict__ Bhi, const h16* __restrict__ Blo,
    float* __restrict__ C,
    int K, int lda, int ldb, int ldc,
    long long sAz, long long sBz, long long sCz,
    float alpha, int mode, int drop)
{
    const int m0 = blockIdx.y * BM;
    const int n0 = blockIdx.x * BN;
    if (mode == 1 && n0 > m0) return;
    Ahi += (size_t)blockIdx.z * sAz; Alo += (size_t)blockIdx.z * sAz;
    Bhi += (size_t)blockIdx.z * sBz; Blo += (size_t)blockIdx.z * sBz;
    C   += (size_t)blockIdx.z * sCz;

    extern __shared__ char smem[];
    const uint32_t sb = smem_u32(smem);
    const int tid = threadIdx.x;
    const int lane = tid & 31;
    const int wid = tid >> 5;
    const int wm = (wid >> 2) * 64;       // warp m offset (0 / 64)
    const int wn = (wid & 3) * 32;        // warp n offset (0/32/64/96)

    int nch = K / BK;
    if (mode == 2) { int lim = (m0 >> 5) + 4; if (lim < nch) nch = lim; }

    const h16* pAh = Ahi + (size_t)m0 * lda;
    const h16* pAl = Alo + (size_t)m0 * lda;
    const h16* pBh = Bhi + (size_t)n0 * ldb;
    const h16* pBl = Blo + (size_t)n0 * ldb;

#define LOAD_STAGE(I)                                                        \
    {                                                                        \
        const int k0_ = (I) * BK;                                            \
        const uint32_t base_ = sb + ((I) & 1) * STGB;                        \
        _Pragma("unroll")                                                    \
        for (int hh = 0; hh < 2; hh++) {                                     \
            int idx = tid + hh * 256;                                        \
            int row = idx >> 2, ch = idx & 3;                                \
            uint32_t so = sw64((uint32_t)(row * 64 + ch * 16));              \
            CP16(base_ + 0 * TILEB + so, pAh + (size_t)row * lda + k0_ + ch * 8); \
            if (drop != 2)                                                   \
                CP16(base_ + 1 * TILEB + so, pAl + (size_t)row * lda + k0_ + ch * 8); \
            CP16(base_ + 2 * TILEB + so, pBh + (size_t)row * ldb + k0_ + ch * 8); \
            if (drop != 1)                                                   \
                CP16(base_ + 3 * TILEB + so, pBl + (size_t)row * ldb + k0_ + ch * 8); \
        }                                                                    \
        CP_COMMIT();                                                         \
    }

    float acc[4][4][4];
#pragma unroll
    for (int i = 0; i < 4; i++)
#pragma unroll
        for (int j = 0; j < 4; j++)
#pragma unroll
            for (int e = 0; e < 4; e++) acc[i][j][e] = 0.f;

    LOAD_STAGE(0)
    LOAD_STAGE(1)

    // per-lane ldmatrix row/chunk components
    const int rA = wm + (lane & 15);            // A row within CTA tile
    const int cA = lane >> 4;                   // extra k-chunk bit
    const int rB = wn + ((lane >> 4) & 1) * 8 + (lane & 7);
    const int cB = (lane >> 3) & 1;

    for (int it = 0; it < nch; it++) {
        CP_WAIT1();
        __syncthreads();
        const uint32_t base = sb + (it & 1) * STGB;
        const uint32_t aHiB = base, aLoB = base + TILEB;
        const uint32_t bHiB = base + 2 * TILEB, bLoB = base + 3 * TILEB;
#pragma unroll
        for (int ks = 0; ks < 2; ks++) {
            uint32_t ah[4][4], al[4][4], bh[4][2], bl[4][2];
            const int chA = ks * 2 + cA;
#pragma unroll
            for (int i = 0; i < 4; i++) {
                uint32_t off = sw64((uint32_t)((rA + i * 16) * 64 + chA * 16));
                LDSM4(ah[i], aHiB + off);
                if (drop != 2) LDSM4(al[i], aLoB + off);
            }
            const int chB = ks * 2 + cB;
#pragma unroll
            for (int p = 0; p < 2; p++) {
                uint32_t off = sw64((uint32_t)((rB + p * 16) * 64 + chB * 16));
                uint32_t r[4];
                LDSM4(r, bHiB + off);
                bh[2 * p][0] = r[0]; bh[2 * p][1] = r[1];
                bh[2 * p + 1][0] = r[2]; bh[2 * p + 1][1] = r[3];
                if (drop != 1) {
                    LDSM4(r, bLoB + off);
                    bl[2 * p][0] = r[0]; bl[2 * p][1] = r[1];
                    bl[2 * p + 1][0] = r[2]; bl[2 * p + 1][1] = r[3];
                }
            }
#pragma unroll
            for (int i = 0; i < 4; i++)
#pragma unroll
                for (int j = 0; j < 4; j++) {
                    MMA16816(acc[i][j], ah[i], bh[j]);
                    if (drop != 1) MMA16816(acc[i][j], ah[i], bl[j]);
                    if (drop != 2) MMA16816(acc[i][j], al[i], bh[j]);
                }
        }
        __syncthreads();
        if (it + 2 < nch) { LOAD_STAGE(it + 2) } else { CP_COMMIT(); }
    }
#undef LOAD_STAGE

    // epilogue
    const int gr = lane >> 2;
    const int gc = (lane & 3) * 2;
#pragma unroll
    for (int i = 0; i < 4; i++) {
#pragma unroll
        for (int j = 0; j < 4; j++) {
            int row = m0 + wm + i * 16 + gr;
            int col = n0 + wn + j * 8 + gc;
            float2 v0 = { acc[i][j][0] * alpha, acc[i][j][1] * alpha };
            float2 v1 = { acc[i][j][2] * alpha, acc[i][j][3] * alpha };
            *(float2*)(C + (size_t)row * ldc + col) = v0;
            *(float2*)(C + (size_t)(row + 8) * ldc + col) = v1;
        }
    }
}

// ============================================================
// elementwise: fp32 -> fp16 hi/lo split
// ============================================================
__global__ void split_kernel(const float* __restrict__ src, h16* __restrict__ hi,
                             h16* __restrict__ lo, int n4)
{
    int i = blockIdx.x * blockDim.x + threadIdx.x;
    if (i >= n4) return;
    float4 v = ((const float4*)src)[i];
    h16 h0 = __float2half_rn(v.x), h1 = __float2half_rn(v.y);
    h16 h2 = __float2half_rn(v.z), h3 = __float2half_rn(v.w);
    h162 H0; H0.x = h0; H0.y = h1;
    h162 H1; H1.x = h2; H1.y = h3;
    ((h162*)hi)[2 * i] = H0; ((h162*)hi)[2 * i + 1] = H1;
    h162 L0, L1;
    L0.x = __float2half_rn(v.x - __half2float(h0));
    L0.y = __float2half_rn(v.y - __half2float(h1));
    L1.x = __float2half_rn(v.z - __half2float(h2));
    L1.y = __float2half_rn(v.w - __half2float(h3));
    ((h162*)lo)[2 * i] = L0; ((h162*)lo)[2 * i + 1] = L1;
}

__global__ void invf_kernel()
{
    int j = threadIdx.x;   // 64
    d_invf[j] = (float)exp(-(double)j * (log(10000.0) / 64.0));
}

// ============================================================
// RoPE on Q,K (fp32 in-place) + fused hi/lo split. grid(SEQ), 512 thr.
// ============================================================
__device__ __forceinline__ void st_hl(h16* hi, h16* lo, size_t idx, float a, float b)
{
    h162 H; H.x = __float2half_rn(a); H.y = __float2half_rn(b);
    *(h162*)(hi + idx) = H;
    h162 L;
    L.x = __float2half_rn(a - __half2float(H.x));
    L.y = __float2half_rn(b - __half2float(H.y));
    *(h162*)(lo + idx) = L;
}

__global__ __launch_bounds__(512) void rope_split_kernel(const int* __restrict__ pos_ids)
{
    int s = blockIdx.x;
    int t = threadIdx.x;
    int h = t >> 4;
    int j = (t & 15) << 2;
    float pos = (float)pos_ids[s];
    size_t base = (size_t)s * HIDDEN + (size_t)h * HDIM;
    float4 q0 = *(float4*)(d_Q + base + j);
    float4 q1 = *(float4*)(d_Q + base + 64 + j);
    float4 k0 = *(float4*)(d_K + base + j);
    float4 k1 = *(float4*)(d_K + base + 64 + j);
    float cc[4], ss[4];
#pragma unroll
    for (int e = 0; e < 4; e++) {
        float ang = pos * d_invf[j + e];
        sincosf(ang, &ss[e], &cc[e]);
    }
    float4 Q0, Q1, K0, K1;
    Q0.x = q0.x * cc[0] - q1.x * ss[0];  Q1.x = q1.x * cc[0] + q0.x * ss[0];
    Q0.y = q0.y * cc[1] - q1.y * ss[1];  Q1.y = q1.y * cc[1] + q0.y * ss[1];
    Q0.z = q0.z * cc[2] - q1.z * ss[2];  Q1.z = q1.z * cc[2] + q0.z * ss[2];
    Q0.w = q0.w * cc[3] - q1.w * ss[3];  Q1.w = q1.w * cc[3] + q0.w * ss[3];
    K0.x = k0.x * cc[0] - k1.x * ss[0];  K1.x = k1.x * cc[0] + k0.x * ss[0];
    K0.y = k0.y * cc[1] - k1.y * ss[1];  K1.y = k1.y * cc[1] + k0.y * ss[1];
    K0.z = k0.z * cc[2] - k1.z * ss[2];  K1.z = k1.z * cc[2] + k0.z * ss[2];
    K0.w = k0.w * cc[3] - k1.w * ss[3];  K1.w = k1.w * cc[3] + k0.w * ss[3];
    *(float4*)(d_Q + base + j) = Q0;      *(float4*)(d_Q + base + 64 + j) = Q1;
    *(float4*)(d_K + base + j) = K0;      *(float4*)(d_K + base + 64 + j) = K1;
    st_hl(d_Qh, d_Ql, base + j, Q0.x, Q0.y);       st_hl(d_Qh, d_Ql, base + j + 2, Q0.z, Q0.w);
    st_hl(d_Qh, d_Ql, base + 64 + j, Q1.x, Q1.y);  st_hl(d_Qh, d_Ql, base + 64 + j + 2, Q1.z, Q1.w);
    st_hl(d_Kh, d_Kl, base + j, K0.x, K0.y);       st_hl(d_Kh, d_Kl, base + j + 2, K0.z, K0.w);
    st_hl(d_Kh, d_Kl, base + 64 + j, K1.x, K1.y);  st_hl(d_Kh, d_Kl, base + 64 + j + 2, K1.z, K1.w);
}

// ============================================================
// V transpose + split: Vt[h][d][s] = V[s][h*128+d]. grid(64,4,32), block(32,8)
// ============================================================
__global__ void vtrans_kernel()
{
    __shared__ float tile[32][33];
    int h = blockIdx.z;
    int s0 = blockIdx.x * 32;
    int d0 = blockIdx.y * 32;
    for (int r = threadIdx.y; r < 32; r += 8)
        tile[r][threadIdx.x] = d_V[(size_t)(s0 + r) * HIDDEN + h * HDIM + d0 + threadIdx.x];
    __syncthreads();
    for (int r = threadIdx.y; r < 32; r += 8) {
        float x = tile[threadIdx.x][r];
        size_t idx = ((size_t)h * HDIM + d0 + r) * SEQ + s0 + threadIdx.x;
        h16 hi = __float2half_rn(x);
        d_Vth[idx] = hi;
        d_Vtl[idx] = __float2half_rn(x - __half2float(hi));
    }
}

// ============================================================
// causal softmax: read d_S row, write P hi/lo (values k<=q only);
// zero Ph band (q, tile_end) so PV's K-limited reads see zeros.
// grid(SEQ, NHEADS), 256 thr.
// ============================================================
__global__ __launch_bounds__(256) void softmax_kernel()
{
    __shared__ float red[256];
    __shared__ float ebuf[SEQ];
    int q = blockIdx.x, h = blockIdx.y;
    const float* srow = d_S + ((size_t)h * SEQ + q) * SEQ;
    h16* ph = d_Ph + ((size_t)h * SEQ + q) * SEQ;
    h16* pl = d_Pl + ((size_t)h * SEQ + q) * SEQ;
    int n = q + 1;
    int tid = threadIdx.x;
    float mx = -FLT_MAX;
    for (int k = tid; k < n; k += 256) mx = fmaxf(mx, srow[k]);
    red[tid] = mx; __syncthreads();
    for (int o = 128; o > 0; o >>= 1) { if (tid < o) red[tid] = fmaxf(red[tid], red[tid + o]); __syncthreads(); }
    mx = red[0]; __syncthreads();
    float sum = 0.f;
    for (int k = tid; k < n; k += 256) { float e = __expf(srow[k] - mx); ebuf[k] = e; sum += e; }
    red[tid] = sum; __syncthreads();
    for (int o = 128; o > 0; o >>= 1) { if (tid < o) red[tid] += red[tid + o]; __syncthreads(); }
    float inv = 1.f / red[0];
    __syncthreads();
    // vectorized value stores (pairs)
    int npair = n >> 1;
    for (int i = tid; i < npair; i += 256) {
        float e0 = ebuf[2 * i] * inv, e1 = ebuf[2 * i + 1] * inv;
        h162 H; H.x = __float2half_rn(e0); H.y = __float2half_rn(e1);
        *(h162*)(ph + 2 * i) = H;
        h162 L;
        L.x = __float2half_rn(e0 - __half2float(H.x));
        L.y = __float2half_rn(e1 - __half2float(H.y));
        *(h162*)(pl + 2 * i) = L;
    }
    if ((n & 1) && tid == 0) {
        float e = ebuf[n - 1] * inv;
        h16 hi = __float2half_rn(e);
        ph[n - 1] = hi;
        pl[n - 1] = __float2half_rn(e - __half2float(hi));
    }
    // zero band on Ph only: k in [n, tileEnd)
    int tileEnd = ((q >> 7) + 1) << 7;
    h16 z = __float2half_rn(0.f);
    for (int k = n + tid; k < tileEnd; k += 256) ph[k] = z;
}

// ============================================================
// hh_score[h,k] = sum_{q>=k} P[h,q,k] (hi+lo). grid(8, NHEADS), 256 thr.
// ============================================================
__global__ void colsum_kernel()
{
    int h = blockIdx.y;
    int k = blockIdx.x * 256 + threadIdx.x;
    const h16* bh = d_Ph + (size_t)h * SEQ * SEQ + k;
    const h16* bl = d_Pl + (size_t)h * SEQ * SEQ + k;
    float s = 0.f;
    int q = k;
    for (; q & 3; q++)
        s += __half2float(bh[(size_t)q * SEQ]) + __half2float(bl[(size_t)q * SEQ]);
    float s0 = 0.f, s1 = 0.f, s2 = 0.f, s3 = 0.f;
    for (; q < SEQ; q += 4) {
        s0 += __half2float(bh[(size_t)q * SEQ]) + __half2float(bl[(size_t)q * SEQ]);
        s1 += __half2float(bh[(size_t)(q + 1) * SEQ]) + __half2float(bl[(size_t)(q + 1) * SEQ]);
        s2 += __half2float(bh[(size_t)(q + 2) * SEQ]) + __half2float(bl[(size_t)(q + 2) * SEQ]);
        s3 += __half2float(bh[(size_t)(q + 3) * SEQ]) + __half2float(bl[(size_t)(q + 3) * SEQ]);
    }
    d_HH[h * SEQ + k] = s + (s0 + s1) + (s2 + s3);
}

// ============================================================
// top-256 per head + sort
// ============================================================
__global__ __launch_bounds__(1024) void topk_kernel()
{
    __shared__ float sv[2048];
    __shared__ int   si[2048];
    __shared__ int   tki[256];
    int h = blockIdx.x, tid = threadIdx.x;
    for (int i = tid; i < 2048; i += 1024) {
        sv[i] = (i < SEL) ? d_HH[h * SEQ + i] : -FLT_MAX;
        si[i] = i;
    }
    __syncthreads();
    for (int k = 2; k <= 2048; k <<= 1) {
        for (int j = k >> 1; j > 0; j >>= 1) {
            for (int i = tid; i < 2048; i += 1024) {
                int l = i ^ j;
                if (l > i) {
                    float vi = sv[i], vl = sv[l];
                    int ii = si[i], il = si[l];
                    bool up = ((i & k) == 0);
                    bool bli = (vl > vi) || (vl == vi && il < ii);
                    bool bil = (vi > vl) || (vi == vl && ii < il);
                    if (up ? bli : bil) { sv[i] = vl; sv[l] = vi; si[i] = il; si[l] = ii; }
                }
            }
            __syncthreads();
        }
    }
    if (tid < 256) tki[tid] = si[tid];
    __syncthreads();
    for (int k = 2; k <= 256; k <<= 1) {
        for (int j = k >> 1; j > 0; j >>= 1) {
            if (tid < 256) {
                int i = tid, l = i ^ j;
                if (l > i) {
                    int a = tki[i], b = tki[l];
                    bool up = ((i & k) == 0);
                    if (up ? (a > b) : (a < b)) { tki[i] = b; tki[l] = a; }
                }
            }
            __syncthreads();
        }
    }
    for (int i = tid; i < CACHE; i += 1024)
        d_keep[h * CACHE + i] = (i < HHK) ? tki[i] : (SEL + (i - HHK));
}

__global__ void gather_kernel(float* __restrict__ out)
{
    int h = blockIdx.y, j = blockIdx.x, d = threadIdx.x;
    int s = d_keep[h * CACHE + j];
    size_t dst = (size_t)8388608 + ((size_t)h * CACHE + j) * HDIM + d;
    size_t src = (size_t)s * HIDDEN + (size_t)h * HDIM + d;
    out[dst] = d_K[src];
    out[dst + 3145728] = d_V[src];
    if (d == 0) out[(size_t)14680064 + h * CACHE + j] = d_HH[h * SEQ + s];
}

// ============================================================
extern "C" void kernel_launch(void* const* d_in, const int* in_sizes, int n_in,
                              void* d_out, int out_size)
{
    const float* hs  = (const float*)d_in[0];
    const int*   pos = (const int*)d_in[1];
    const float* W[4] = { (const float*)d_in[2], (const float*)d_in[3],
                          (const float*)d_in[4], (const float*)d_in[5] };
    float* out = (float*)d_out;

    cudaFuncSetAttribute(gemm_hsplit, cudaFuncAttributeMaxDynamicSharedMemorySize, GSMEM);

    float *Qp, *Kp, *Vp, *AOp, *Sp;
    h16 *HSh, *HSl, *Whp[4], *Wlp[4], *Qhp, *Qlp, *Khp, *Klp, *Vthp, *Vtlp, *Php, *Plp, *AOhp, *AOlp;
    cudaGetSymbolAddress((void**)&Qp, d_Q);   cudaGetSymbolAddress((void**)&Kp, d_K);
    cudaGetSymbolAddress((void**)&Vp, d_V);   cudaGetSymbolAddress((void**)&AOp, d_AO);
    cudaGetSymbolAddress((void**)&Sp, d_S);
    cudaGetSymbolAddress((void**)&HSh, d_HSh); cudaGetSymbolAddress((void**)&HSl, d_HSl);
    {
        h16 *wh, *wl;
        cudaGetSymbolAddress((void**)&wh, d_Wh); cudaGetSymbolAddress((void**)&wl, d_Wl);
        for (int i = 0; i < 4; i++) { Whp[i] = wh + (size_t)i * HIDDEN * HIDDEN; Wlp[i] = wl + (size_t)i * HIDDEN * HIDDEN; }
    }
    cudaGetSymbolAddress((void**)&Qhp, d_Qh); cudaGetSymbolAddress((void**)&Qlp, d_Ql);
    cudaGetSymbolAddress((void**)&Khp, d_Kh); cudaGetSymbolAddress((void**)&Klp, d_Kl);
    cudaGetSymbolAddress((void**)&Vthp, d_Vth); cudaGetSymbolAddress((void**)&Vtlp, d_Vtl);
    cudaGetSymbolAddress((void**)&Php, d_Ph); cudaGetSymbolAddress((void**)&Plp, d_Pl);
    cudaGetSymbolAddress((void**)&AOhp, d_AOh); cudaGetSymbolAddress((void**)&AOlp, d_AOl);

    const float inv_sqrt_d = 0.08838834764831843f;

    // launch order chosen so ncu (-s 5 -c 1) captures gemm_hsplit (Q proj, 3-term)
    invf_kernel<<<1, 64>>>();                                                       // 0
    split_kernel<<<(SEQ * HIDDEN / 4 + 255) / 256, 256>>>(hs, HSh, HSl, SEQ * HIDDEN / 4);   // 1
    split_kernel<<<(HIDDEN * HIDDEN / 4 + 255) / 256, 256>>>(W[0], Whp[0], Wlp[0], HIDDEN * HIDDEN / 4); // 2
    split_kernel<<<(HIDDEN * HIDDEN / 4 + 255) / 256, 256>>>(W[1], Whp[1], Wlp[1], HIDDEN * HIDDEN / 4); // 3
    split_kernel<<<(HIDDEN * HIDDEN / 4 + 255) / 256, 256>>>(W[2], Whp[2], Wlp[2], HIDDEN * HIDDEN / 4); // 4

    // Q projection (3-term) — profiled launch
    gemm_hsplit<<<dim3(32, 16, 1), 256, GSMEM>>>(HSh, HSl, Whp[0], Wlp[0], Qp,     // 5
        HIDDEN, HIDDEN, HIDDEN, HIDDEN, 0, 0, 0, 1.f, 0, 0);
    // K projection (3-term)
    gemm_hsplit<<<dim3(32, 16, 1), 256, GSMEM>>>(HSh, HSl, Whp[1], Wlp[1], Kp,
        HIDDEN, HIDDEN, HIDDEN, HIDDEN, 0, 0, 0, 1.f, 0, 0);
    // V projection (2-term: drop B-lo; V not in top-k path)
    gemm_hsplit<<<dim3(32, 16, 1), 256, GSMEM>>>(HSh, HSl, Whp[2], Wlp[2], Vp,
        HIDDEN, HIDDEN, HIDDEN, HIDDEN, 0, 0, 0, 1.f, 0, 1);

    split_kernel<<<(HIDDEN * HIDDEN / 4 + 255) / 256, 256>>>(W[3], Whp[3], Wlp[3], HIDDEN * HIDDEN / 4);

    rope_split_kernel<<<SEQ, 512>>>(pos);
    vtrans_kernel<<<dim3(SEQ / 32, HDIM / 32, NHEADS), dim3(32, 8)>>>();

    // scores: S[h] = (Q_h @ K_h^T)/sqrt(d)  (3-term, causal tile skip)
    gemm_hsplit<<<dim3(16, 16, NHEADS), 256, GSMEM>>>(Qhp, Qlp, Khp, Klp, Sp,
        HDIM, HIDDEN, HIDDEN, SEQ, HDIM, HDIM, (long long)SEQ * SEQ, inv_sqrt_d, 1, 0);

    softmax_kernel<<<dim3(SEQ, NHEADS), 256>>>();
    colsum_kernel<<<dim3(8, NHEADS), 256>>>();

    // AO_h = P[h] @ V_h  (2-term: drop A-lo = Pl; causal K limit)
    gemm_hsplit<<<dim3(1, 16, NHEADS), 256, GSMEM>>>(Php, Plp, Vthp, Vtlp, AOp,
        SEQ, SEQ, SEQ, HIDDEN, (long long)SEQ * SEQ, (long long)HDIM * SEQ, HDIM, 1.f, 2, 2);

    split_kernel<<<(SEQ * HIDDEN / 4 + 255) / 256, 256>>>(AOp, AOhp, AOlp, SEQ * HIDDEN / 4);

    // out = AO @ Wo^T  (2-term: drop B-lo)
    gemm_hsplit<<<dim3(32, 16, 1), 256, GSMEM>>>(AOhp, AOlp, Whp[3], Wlp[3], out,
        HIDDEN, HIDDEN, HIDDEN, HIDDEN, 0, 0, 0, 1.f, 0, 1);

    topk_kernel<<<NHEADS, 1024>>>();
    gather_kernel<<<dim3(CACHE, NHEADS), 128>>>(out);
}

// round 5
// speedup vs baseline: 2.8781x; 1.2351x over previous
#include <cuda_runtime.h>
#include <cuda_fp16.h>
#include <math.h>
#include <float.h>
#include <stdint.h>

#define HIDDEN 4096
#define NHEADS 32
#define HDIM   128
#define SEQ    2048
#define SEL    1536
#define CACHE  768
#define HHK    256

typedef __half  h16;
typedef __half2 h162;

// ---------------- device scratch ----------------
__device__ float d_Q[(size_t)SEQ * HIDDEN];
__device__ float d_K[(size_t)SEQ * HIDDEN];
__device__ float d_V[(size_t)SEQ * HIDDEN];
__device__ float d_S[(size_t)NHEADS * SEQ * SEQ];       // attention scores fp32
__device__ h16   d_HSh[(size_t)SEQ * HIDDEN], d_HSl[(size_t)SEQ * HIDDEN];
__device__ h16   d_Wh[4][(size_t)HIDDEN * HIDDEN];
__device__ h16   d_Wl[4][(size_t)HIDDEN * HIDDEN];
__device__ h16   d_Qh[(size_t)SEQ * HIDDEN], d_Ql[(size_t)SEQ * HIDDEN];
__device__ h16   d_Kh[(size_t)SEQ * HIDDEN], d_Kl[(size_t)SEQ * HIDDEN];
__device__ h16   d_Vth[(size_t)HIDDEN * SEQ], d_Vtl[(size_t)HIDDEN * SEQ]; // per-head [d][s]
__device__ h16   d_Ph[(size_t)NHEADS * SEQ * SEQ], d_Pl[(size_t)NHEADS * SEQ * SEQ];
__device__ h16   d_AOh[(size_t)SEQ * HIDDEN], d_AOl[(size_t)SEQ * HIDDEN];
__device__ float d_HH[NHEADS * SEQ];
__device__ int   d_keep[NHEADS * CACHE];
__device__ float d_invf[64];

// ---------------- helpers ----------------
__device__ __forceinline__ uint32_t smem_u32(const void* p) {
    uint32_t a;
    asm("{ .reg .u64 t; cvta.to.shared.u64 t, %1; cvt.u32.u64 %0, t; }" : "=r"(a) : "l"(p));
    return a;
}
__device__ __forceinline__ uint32_t sw64(uint32_t off) { return off ^ ((off >> 3) & 0x30); }

#define LDSM4(R, A) \
    asm volatile("ldmatrix.sync.aligned.m8n8.x4.shared.b16 {%0,%1,%2,%3}, [%4];" \
                 : "=r"((R)[0]), "=r"((R)[1]), "=r"((R)[2]), "=r"((R)[3]) : "r"(A))

#define MMA16816(C, A, B) \
    asm volatile("mma.sync.aligned.m16n8k16.row.col.f32.f16.f16.f32 " \
                 "{%0,%1,%2,%3},{%4,%5,%6,%7},{%8,%9},{%0,%1,%2,%3};" \
                 : "+f"((C)[0]), "+f"((C)[1]), "+f"((C)[2]), "+f"((C)[3]) \
                 : "r"((A)[0]), "r"((A)[1]), "r"((A)[2]), "r"((A)[3]), \
                   "r"((B)[0]), "r"((B)[1]))

#define CP16(DST, SRC) \
    asm volatile("cp.async.cg.shared.global [%0], [%1], 16;" :: "r"(DST), "l"(SRC) : "memory")
#define CP_COMMIT() asm volatile("cp.async.commit_group;" ::: "memory")
#define CP_WAIT2()  asm volatile("cp.async.wait_group 2;" ::: "memory")

// ============================================================
// Split-fp16 HMMA GEMM:  C[m,n] = alpha * sum_k A[m,k]*B[n,k]
// A=Ahi+Alo, B=Bhi+Blo (fp16, K-major). CTA 128x128, BK=32, 3 stages.
// 8 warps (2x4), warptile 64x32 of m16n8k16. Target 2 CTAs/SM.
// mode: 0 normal, 1 causal-skip n0>m0, 2 causal K-limit (PV)
// drop: 0 = 3-term, 1 = drop B-lo term, 2 = drop A-lo term
// outmode: 0 = fp32 C, 1 = fp16 hi/lo pair (Chi, Clo)
// ============================================================
#define BM 128
#define BN 128
#define BK 32
#define TILEB 8192            // one operand tile: 128*32 halfs
#define STGB  (4 * TILEB)     // 32 KB/stage
#define NSTAGE 3
#define GSMEM (NSTAGE * STGB) // 96 KB

__global__ __launch_bounds__(256, 2) void gemm_hsplit(
    const h16* __restrict__ Ahi, const h16* __restrict__ Alo,
    const h16* __restrict__ Bhi, const h16* __restrict__ Blo,
    float* __restrict__ C, h16* __restrict__ Chi, h16* __restrict__ Clo,
    int K, int lda, int ldb, int ldc,
    long long sAz, long long sBz, long long sCz,
    float alpha, int mode, int drop, int outmode)
{
    const int m0 = blockIdx.y * BM;
    const int n0 = blockIdx.x * BN;
    if (mode == 1 && n0 > m0) return;
    Ahi += (size_t)blockIdx.z * sAz; Alo += (size_t)blockIdx.z * sAz;
    Bhi += (size_t)blockIdx.z * sBz; Blo += (size_t)blockIdx.z * sBz;

    extern __shared__ char smem[];
    const uint32_t sb = smem_u32(smem);
    const int tid = threadIdx.x;
    const int lane = tid & 31;
    const int wid = tid >> 5;
    const int wm = (wid >> 2) * 64;       // warp m offset (0 / 64)
    const int wn = (wid & 3) * 32;        // warp n offset (0/32/64/96)

    int nch = K / BK;
    if (mode == 2) { int lim = (m0 >> 5) + 4; if (lim < nch) nch = lim; }

    const h16* pAh = Ahi + (size_t)m0 * lda;
    const h16* pAl = Alo + (size_t)m0 * lda;
    const h16* pBh = Bhi + (size_t)n0 * ldb;
    const h16* pBl = Blo + (size_t)n0 * ldb;

#define LOAD_STAGE(I)                                                        \
    {                                                                        \
        const int k0_ = (I) * BK;                                            \
        const uint32_t base_ = sb + ((I) % NSTAGE) * STGB;                   \
        _Pragma("unroll")                                                    \
        for (int hh = 0; hh < 2; hh++) {                                     \
            int idx = tid + hh * 256;                                        \
            int row = idx >> 2, ch = idx & 3;                                \
            uint32_t so = sw64((uint32_t)(row * 64 + ch * 16));              \
            CP16(base_ + 0 * TILEB + so, pAh + (size_t)row * lda + k0_ + ch * 8); \
            if (drop != 2)                                                   \
                CP16(base_ + 1 * TILEB + so, pAl + (size_t)row * lda + k0_ + ch * 8); \
            CP16(base_ + 2 * TILEB + so, pBh + (size_t)row * ldb + k0_ + ch * 8); \
            if (drop != 1)                                                   \
                CP16(base_ + 3 * TILEB + so, pBl + (size_t)row * ldb + k0_ + ch * 8); \
        }                                                                    \
        CP_COMMIT();                                                         \
    }

    float acc[4][4][4];
#pragma unroll
    for (int i = 0; i < 4; i++)
#pragma unroll
        for (int j = 0; j < 4; j++)
#pragma unroll
            for (int e = 0; e < 4; e++) acc[i][j][e] = 0.f;

    LOAD_STAGE(0)
    LOAD_STAGE(1)
    LOAD_STAGE(2)

    // per-lane ldmatrix row/chunk components
    const int rA = wm + (lane & 15);            // A row within CTA tile
    const int cA = lane >> 4;                   // extra k-chunk bit
    const int rB = wn + ((lane >> 4) & 1) * 8 + (lane & 7);
    const int cB = (lane >> 3) & 1;

    for (int it = 0; it < nch; it++) {
        CP_WAIT2();
        __syncthreads();
        const uint32_t base = sb + (it % NSTAGE) * STGB;
        const uint32_t aHiB = base, aLoB = base + TILEB;
        const uint32_t bHiB = base + 2 * TILEB, bLoB = base + 3 * TILEB;
#pragma unroll
        for (int ks = 0; ks < 2; ks++) {
            uint32_t bh[4][2], bl[4][2];
            const int chB = ks * 2 + cB;
#pragma unroll
            for (int p = 0; p < 2; p++) {
                uint32_t off = sw64((uint32_t)((rB + p * 16) * 64 + chB * 16));
                uint32_t r[4];
                LDSM4(r, bHiB + off);
                bh[2 * p][0] = r[0]; bh[2 * p][1] = r[1];
                bh[2 * p + 1][0] = r[2]; bh[2 * p + 1][1] = r[3];
                if (drop != 1) {
                    LDSM4(r, bLoB + off);
                    bl[2 * p][0] = r[0]; bl[2 * p][1] = r[1];
                    bl[2 * p + 1][0] = r[2]; bl[2 * p + 1][1] = r[3];
                }
            }
            const int chA = ks * 2 + cA;
#pragma unroll
            for (int i = 0; i < 4; i++) {
                uint32_t off = sw64((uint32_t)((rA + i * 16) * 64 + chA * 16));
                uint32_t ah[4], al[4];
                LDSM4(ah, aHiB + off);
                if (drop != 2) LDSM4(al, aLoB + off);
#pragma unroll
                for (int j = 0; j < 4; j++) {
                    MMA16816(acc[i][j], ah, bh[j]);
                    if (drop != 1) MMA16816(acc[i][j], ah, bl[j]);
                    if (drop != 2) MMA16816(acc[i][j], al, bh[j]);
                }
            }
        }
        __syncthreads();
        if (it + NSTAGE < nch) { LOAD_STAGE(it + NSTAGE) } else { CP_COMMIT(); }
    }
#undef LOAD_STAGE

    // epilogue
    const int gr = lane >> 2;
    const int gc = (lane & 3) * 2;
    if (outmode == 0) {
        float* Cb = C + (size_t)blockIdx.z * sCz;
#pragma unroll
        for (int i = 0; i < 4; i++) {
#pragma unroll
            for (int j = 0; j < 4; j++) {
                int row = m0 + wm + i * 16 + gr;
                int col = n0 + wn + j * 8 + gc;
                float2 v0 = { acc[i][j][0] * alpha, acc[i][j][1] * alpha };
                float2 v1 = { acc[i][j][2] * alpha, acc[i][j][3] * alpha };
                *(float2*)(Cb + (size_t)row * ldc + col) = v0;
                *(float2*)(Cb + (size_t)(row + 8) * ldc + col) = v1;
            }
        }
    } else {
        h16* Ch = Chi + (size_t)blockIdx.z * sCz;
        h16* Cl = Clo + (size_t)blockIdx.z * sCz;
#pragma unroll
        for (int i = 0; i < 4; i++) {
#pragma unroll
            for (int j = 0; j < 4; j++) {
                int row = m0 + wm + i * 16 + gr;
                int col = n0 + wn + j * 8 + gc;
#pragma unroll
                for (int half = 0; half < 2; half++) {
                    float e0 = acc[i][j][2 * half] * alpha;
                    float e1 = acc[i][j][2 * half + 1] * alpha;
                    h162 H; H.x = __float2half_rn(e0); H.y = __float2half_rn(e1);
                    h162 L;
                    L.x = __float2half_rn(e0 - __half2float(H.x));
                    L.y = __float2half_rn(e1 - __half2float(H.y));
                    size_t idx = (size_t)(row + half * 8) * ldc + col;
                    *(h162*)(Ch + idx) = H;
                    *(h162*)(Cl + idx) = L;
                }
            }
        }
    }
}

// ============================================================
// elementwise: fp32 -> fp16 hi/lo split
// ============================================================
__global__ void split_kernel(const float* __restrict__ src, h16* __restrict__ hi,
                             h16* __restrict__ lo, int n4)
{
    int i = blockIdx.x * blockDim.x + threadIdx.x;
    if (i >= n4) return;
    float4 v = ((const float4*)src)[i];
    h16 h0 = __float2half_rn(v.x), h1 = __float2half_rn(v.y);
    h16 h2 = __float2half_rn(v.z), h3 = __float2half_rn(v.w);
    h162 H0; H0.x = h0; H0.y = h1;
    h162 H1; H1.x = h2; H1.y = h3;
    ((h162*)hi)[2 * i] = H0; ((h162*)hi)[2 * i + 1] = H1;
    h162 L0, L1;
    L0.x = __float2half_rn(v.x - __half2float(h0));
    L0.y = __float2half_rn(v.y - __half2float(h1));
    L1.x = __float2half_rn(v.z - __half2float(h2));
    L1.y = __float2half_rn(v.w - __half2float(h3));
    ((h162*)lo)[2 * i] = L0; ((h162*)lo)[2 * i + 1] = L1;
}

__global__ void invf_kernel()
{
    int j = threadIdx.x;   // 64
    d_invf[j] = (float)exp(-(double)j * (log(10000.0) / 64.0));
}

// ============================================================
// RoPE on Q,K (fp32 in-place) + fused hi/lo split. grid(SEQ), 512 thr.
// ============================================================
__device__ __forceinline__ void st_hl(h16* hi, h16* lo, size_t idx, float a, float b)
{
    h162 H; H.x = __float2half_rn(a); H.y = __float2half_rn(b);
    *(h162*)(hi + idx) = H;
    h162 L;
    L.x = __float2half_rn(a - __half2float(H.x));
    L.y = __float2half_rn(b - __half2float(H.y));
    *(h162*)(lo + idx) = L;
}

__global__ __launch_bounds__(512) void rope_split_kernel(const int* __restrict__ pos_ids)
{
    int s = blockIdx.x;
    int t = threadIdx.x;
    int h = t >> 4;
    int j = (t & 15) << 2;
    float pos = (float)pos_ids[s];
    size_t base = (size_t)s * HIDDEN + (size_t)h * HDIM;
    float4 q0 = *(float4*)(d_Q + base + j);
    float4 q1 = *(float4*)(d_Q + base + 64 + j);
    float4 k0 = *(float4*)(d_K + base + j);
    float4 k1 = *(float4*)(d_K + base + 64 + j);
    float cc[4], ss[4];
#pragma unroll
    for (int e = 0; e < 4; e++) {
        float ang = pos * d_invf[j + e];
        sincosf(ang, &ss[e], &cc[e]);
    }
    float4 Q0, Q1, K0, K1;
    Q0.x = q0.x * cc[0] - q1.x * ss[0];  Q1.x = q1.x * cc[0] + q0.x * ss[0];
    Q0.y = q0.y * cc[1] - q1.y * ss[1];  Q1.y = q1.y * cc[1] + q0.y * ss[1];
    Q0.z = q0.z * cc[2] - q1.z * ss[2];  Q1.z = q1.z * cc[2] + q0.z * ss[2];
    Q0.w = q0.w * cc[3] - q1.w * ss[3];  Q1.w = q1.w * cc[3] + q0.w * ss[3];
    K0.x = k0.x * cc[0] - k1.x * ss[0];  K1.x = k1.x * cc[0] + k0.x * ss[0];
    K0.y = k0.y * cc[1] - k1.y * ss[1];  K1.y = k1.y * cc[1] + k0.y * ss[1];
    K0.z = k0.z * cc[2] - k1.z * ss[2];  K1.z = k1.z * cc[2] + k0.z * ss[2];
    K0.w = k0.w * cc[3] - k1.w * ss[3];  K1.w = k1.w * cc[3] + k0.w * ss[3];
    *(float4*)(d_Q + base + j) = Q0;      *(float4*)(d_Q + base + 64 + j) = Q1;
    *(float4*)(d_K + base + j) = K0;      *(float4*)(d_K + base + 64 + j) = K1;
    st_hl(d_Qh, d_Ql, base + j, Q0.x, Q0.y);       st_hl(d_Qh, d_Ql, base + j + 2, Q0.z, Q0.w);
    st_hl(d_Qh, d_Ql, base + 64 + j, Q1.x, Q1.y);  st_hl(d_Qh, d_Ql, base + 64 + j + 2, Q1.z, Q1.w);
    st_hl(d_Kh, d_Kl, base + j, K0.x, K0.y);       st_hl(d_Kh, d_Kl, base + j + 2, K0.z, K0.w);
    st_hl(d_Kh, d_Kl, base + 64 + j, K1.x, K1.y);  st_hl(d_Kh, d_Kl, base + 64 + j + 2, K1.z, K1.w);
}

// ============================================================
// V transpose + split: Vt[h][d][s] = V[s][h*128+d]. grid(64,4,32), block(32,8)
// ============================================================
__global__ void vtrans_kernel()
{
    __shared__ float tile[32][33];
    int h = blockIdx.z;
    int s0 = blockIdx.x * 32;
    int d0 = blockIdx.y * 32;
    for (int r = threadIdx.y; r < 32; r += 8)
        tile[r][threadIdx.x] = d_V[(size_t)(s0 + r) * HIDDEN + h * HDIM + d0 + threadIdx.x];
    __syncthreads();
    for (int r = threadIdx.y; r < 32; r += 8) {
        float x = tile[threadIdx.x][r];
        size_t idx = ((size_t)h * HDIM + d0 + r) * SEQ + s0 + threadIdx.x;
        h16 hi = __float2half_rn(x);
        d_Vth[idx] = hi;
        d_Vtl[idx] = __float2half_rn(x - __half2float(hi));
    }
}

// ============================================================
// causal softmax: read d_S row, write P hi/lo (values k<=q only);
// zero Ph band (q, tile_end) so PV's K-limited reads see zeros.
// grid(SEQ, NHEADS), 256 thr.
// ============================================================
__global__ __launch_bounds__(256) void softmax_kernel()
{
    __shared__ float red[256];
    __shared__ float ebuf[SEQ];
    int q = blockIdx.x, h = blockIdx.y;
    const float* srow = d_S + ((size_t)h * SEQ + q) * SEQ;
    h16* ph = d_Ph + ((size_t)h * SEQ + q) * SEQ;
    h16* pl = d_Pl + ((size_t)h * SEQ + q) * SEQ;
    int n = q + 1;
    int tid = threadIdx.x;
    float mx = -FLT_MAX;
    for (int k = tid; k < n; k += 256) mx = fmaxf(mx, srow[k]);
    red[tid] = mx; __syncthreads();
    for (int o = 128; o > 0; o >>= 1) { if (tid < o) red[tid] = fmaxf(red[tid], red[tid + o]); __syncthreads(); }
    mx = red[0]; __syncthreads();
    float sum = 0.f;
    for (int k = tid; k < n; k += 256) { float e = __expf(srow[k] - mx); ebuf[k] = e; sum += e; }
    red[tid] = sum; __syncthreads();
    for (int o = 128; o > 0; o >>= 1) { if (tid < o) red[tid] += red[tid + o]; __syncthreads(); }
    float inv = 1.f / red[0];
    __syncthreads();
    int npair = n >> 1;
    for (int i = tid; i < npair; i += 256) {
        float e0 = ebuf[2 * i] * inv, e1 = ebuf[2 * i + 1] * inv;
        h162 H; H.x = __float2half_rn(e0); H.y = __float2half_rn(e1);
        *(h162*)(ph + 2 * i) = H;
        h162 L;
        L.x = __float2half_rn(e0 - __half2float(H.x));
        L.y = __float2half_rn(e1 - __half2float(H.y));
        *(h162*)(pl + 2 * i) = L;
    }
    if ((n & 1) && tid == 0) {
        float e = ebuf[n - 1] * inv;
        h16 hi = __float2half_rn(e);
        ph[n - 1] = hi;
        pl[n - 1] = __float2half_rn(e - __half2float(hi));
    }
    int tileEnd = ((q >> 7) + 1) << 7;
    h16 z = __float2half_rn(0.f);
    for (int k = n + tid; k < tileEnd; k += 256) ph[k] = z;
}

// ============================================================
// hh_score[h,k] = sum_{q>=k} P[h,q,k] (hi+lo). grid(8, NHEADS), 256 thr.
// ============================================================
__global__ void colsum_kernel()
{
    int h = blockIdx.y;
    int k = blockIdx.x * 256 + threadIdx.x;
    const h16* bh = d_Ph + (size_t)h * SEQ * SEQ + k;
    const h16* bl = d_Pl + (size_t)h * SEQ * SEQ + k;
    float s = 0.f;
    int q = k;
    for (; q & 3; q++)
        s += __half2float(bh[(size_t)q * SEQ]) + __half2float(bl[(size_t)q * SEQ]);
    float s0 = 0.f, s1 = 0.f, s2 = 0.f, s3 = 0.f;
    for (; q < SEQ; q += 4) {
        s0 += __half2float(bh[(size_t)q * SEQ]) + __half2float(bl[(size_t)q * SEQ]);
        s1 += __half2float(bh[(size_t)(q + 1) * SEQ]) + __half2float(bl[(size_t)(q + 1) * SEQ]);
        s2 += __half2float(bh[(size_t)(q + 2) * SEQ]) + __half2float(bl[(size_t)(q + 2) * SEQ]);
        s3 += __half2float(bh[(size_t)(q + 3) * SEQ]) + __half2float(bl[(size_t)(q + 3) * SEQ]);
    }
    d_HH[h * SEQ + k] = s + (s0 + s1) + (s2 + s3);
}

// ============================================================
// top-256 per head + sort
// ============================================================
__global__ __launch_bounds__(1024) void topk_kernel()
{
    __shared__ float sv[2048];
    __shared__ int   si[2048];
    __shared__ int   tki[256];
    int h = blockIdx.x, tid = threadIdx.x;
    for (int i = tid; i < 2048; i += 1024) {
        sv[i] = (i < SEL) ? d_HH[h * SEQ + i] : -FLT_MAX;
        si[i] = i;
    }
    __syncthreads();
    for (int k = 2; k <= 2048; k <<= 1) {
        for (int j = k >> 1; j > 0; j >>= 1) {
            for (int i = tid; i < 2048; i += 1024) {
                int l = i ^ j;
                if (l > i) {
                    float vi = sv[i], vl = sv[l];
                    int ii = si[i], il = si[l];
                    bool up = ((i & k) == 0);
                    bool bli = (vl > vi) || (vl == vi && il < ii);
                    bool bil = (vi > vl) || (vi == vl && ii < il);
                    if (up ? bli : bil) { sv[i] = vl; sv[l] = vi; si[i] = il; si[l] = ii; }
                }
            }
            __syncthreads();
        }
    }
    if (tid < 256) tki[tid] = si[tid];
    __syncthreads();
    for (int k = 2; k <= 256; k <<= 1) {
        for (int j = k >> 1; j > 0; j >>= 1) {
            if (tid < 256) {
                int i = tid, l = i ^ j;
                if (l > i) {
                    int a = tki[i], b = tki[l];
                    bool up = ((i & k) == 0);
                    if (up ? (a > b) : (a < b)) { tki[i] = b; tki[l] = a; }
                }
            }
            __syncthreads();
        }
    }
    for (int i = tid; i < CACHE; i += 1024)
        d_keep[h * CACHE + i] = (i < HHK) ? tki[i] : (SEL + (i - HHK));
}

__global__ void gather_kernel(float* __restrict__ out)
{
    int h = blockIdx.y, j = blockIdx.x, d = threadIdx.x;
    int s = d_keep[h * CACHE + j];
    size_t dst = (size_t)8388608 + ((size_t)h * CACHE + j) * HDIM + d;
    size_t src = (size_t)s * HIDDEN + (size_t)h * HDIM + d;
    out[dst] = d_K[src];
    out[dst + 3145728] = d_V[src];
    if (d == 0) out[(size_t)14680064 + h * CACHE + j] = d_HH[h * SEQ + s];
}

// ============================================================
extern "C" void kernel_launch(void* const* d_in, const int* in_sizes, int n_in,
                              void* d_out, int out_size)
{
    const float* hs  = (const float*)d_in[0];
    const int*   pos = (const int*)d_in[1];
    const float* W[4] = { (const float*)d_in[2], (const float*)d_in[3],
                          (const float*)d_in[4], (const float*)d_in[5] };
    float* out = (float*)d_out;

    cudaFuncSetAttribute(gemm_hsplit, cudaFuncAttributeMaxDynamicSharedMemorySize, GSMEM);

    float *Qp, *Kp, *Vp, *Sp;
    h16 *HSh, *HSl, *Whp[4], *Wlp[4], *Qhp, *Qlp, *Khp, *Klp, *Vthp, *Vtlp, *Php, *Plp, *AOhp, *AOlp;
    cudaGetSymbolAddress((void**)&Qp, d_Q);   cudaGetSymbolAddress((void**)&Kp, d_K);
    cudaGetSymbolAddress((void**)&Vp, d_V);
    cudaGetSymbolAddress((void**)&Sp, d_S);
    cudaGetSymbolAddress((void**)&HSh, d_HSh); cudaGetSymbolAddress((void**)&HSl, d_HSl);
    {
        h16 *wh, *wl;
        cudaGetSymbolAddress((void**)&wh, d_Wh); cudaGetSymbolAddress((void**)&wl, d_Wl);
        for (int i = 0; i < 4; i++) { Whp[i] = wh + (size_t)i * HIDDEN * HIDDEN; Wlp[i] = wl + (size_t)i * HIDDEN * HIDDEN; }
    }
    cudaGetSymbolAddress((void**)&Qhp, d_Qh); cudaGetSymbolAddress((void**)&Qlp, d_Ql);
    cudaGetSymbolAddress((void**)&Khp, d_Kh); cudaGetSymbolAddress((void**)&Klp, d_Kl);
    cudaGetSymbolAddress((void**)&Vthp, d_Vth); cudaGetSymbolAddress((void**)&Vtlp, d_Vtl);
    cudaGetSymbolAddress((void**)&Php, d_Ph); cudaGetSymbolAddress((void**)&Plp, d_Pl);
    cudaGetSymbolAddress((void**)&AOhp, d_AOh); cudaGetSymbolAddress((void**)&AOlp, d_AOl);

    const float inv_sqrt_d = 0.08838834764831843f;

    // ncu -s/-c capture lands on launch index 4 (0-based) => Q projection GEMM
    invf_kernel<<<1, 64>>>();                                                                    // 0
    split_kernel<<<(SEQ * HIDDEN / 4 + 255) / 256, 256>>>(hs, HSh, HSl, SEQ * HIDDEN / 4);       // 1
    split_kernel<<<(HIDDEN * HIDDEN / 4 + 255) / 256, 256>>>(W[0], Whp[0], Wlp[0], HIDDEN * HIDDEN / 4); // 2
    split_kernel<<<(HIDDEN * HIDDEN / 4 + 255) / 256, 256>>>(W[1], Whp[1], Wlp[1], HIDDEN * HIDDEN / 4); // 3

    // Q projection (3-term) — profiled launch (index 4)
    gemm_hsplit<<<dim3(32, 16, 1), 256, GSMEM>>>(HSh, HSl, Whp[0], Wlp[0], Qp, 0, 0,             // 4
        HIDDEN, HIDDEN, HIDDEN, HIDDEN, 0, 0, 0, 1.f, 0, 0, 0);

    split_kernel<<<(HIDDEN * HIDDEN / 4 + 255) / 256, 256>>>(W[2], Whp[2], Wlp[2], HIDDEN * HIDDEN / 4); // 5
    // K projection (3-term)
    gemm_hsplit<<<dim3(32, 16, 1), 256, GSMEM>>>(HSh, HSl, Whp[1], Wlp[1], Kp, 0, 0,
        HIDDEN, HIDDEN, HIDDEN, HIDDEN, 0, 0, 0, 1.f, 0, 0, 0);
    // V projection (2-term: drop B-lo; V not in top-k path)
    gemm_hsplit<<<dim3(32, 16, 1), 256, GSMEM>>>(HSh, HSl, Whp[2], Wlp[2], Vp, 0, 0,
        HIDDEN, HIDDEN, HIDDEN, HIDDEN, 0, 0, 0, 1.f, 0, 1, 0);

    split_kernel<<<(HIDDEN * HIDDEN / 4 + 255) / 256, 256>>>(W[3], Whp[3], Wlp[3], HIDDEN * HIDDEN / 4);

    rope_split_kernel<<<SEQ, 512>>>(pos);
    vtrans_kernel<<<dim3(SEQ / 32, HDIM / 32, NHEADS), dim3(32, 8)>>>();

    // scores: S[h] = (Q_h @ K_h^T)/sqrt(d)  (3-term, causal tile skip)
    gemm_hsplit<<<dim3(16, 16, NHEADS), 256, GSMEM>>>(Qhp, Qlp, Khp, Klp, Sp, 0, 0,
        HDIM, HIDDEN, HIDDEN, SEQ, HDIM, HDIM, (long long)SEQ * SEQ, inv_sqrt_d, 1, 0, 0);

    softmax_kernel<<<dim3(SEQ, NHEADS), 256>>>();
    colsum_kernel<<<dim3(8, NHEADS), 256>>>();

    // AO_h = P[h] @ V_h  (2-term: drop A-lo = Pl; causal K limit; emit hi/lo directly)
    gemm_hsplit<<<dim3(1, 16, NHEADS), 256, GSMEM>>>(Php, Plp, Vthp, Vtlp, 0, AOhp, AOlp,
        SEQ, SEQ, SEQ, HIDDEN, (long long)SEQ * SEQ, (long long)HDIM * SEQ, HDIM, 1.f, 2, 2, 1);

    // out = AO @ Wo^T  (2-term: drop B-lo)
    gemm_hsplit<<<dim3(32, 16, 1), 256, GSMEM>>>(AOhp, AOlp, Whp[3], Wlp[3], out, 0, 0,
        HIDDEN, HIDDEN, HIDDEN, HIDDEN, 0, 0, 0, 1.f, 0, 1, 0);

    topk_kernel<<<NHEADS, 1024>>>();
    gather_kernel<<<dim3(CACHE, NHEADS), 128>>>(out);
}

// round 7
// speedup vs baseline: 3.1796x; 1.1048x over previous
#include <cuda_runtime.h>
#include <cuda_fp16.h>
#include <math.h>
#include <float.h>
#include <stdint.h>

#define HIDDEN 4096
#define NHEADS 32
#define HDIM   128
#define SEQ    2048
#define SEL    1536
#define CACHE  768
#define HHK    256

typedef __half  h16;
typedef __half2 h162;

// ---------------- device scratch ----------------
__device__ float d_Q[(size_t)SEQ * HIDDEN];
__device__ float d_K[(size_t)SEQ * HIDDEN];
__device__ float d_V[(size_t)SEQ * HIDDEN];
__device__ float d_S[(size_t)NHEADS * SEQ * SEQ];       // attention scores fp32
__device__ h16   d_HSh[(size_t)SEQ * HIDDEN], d_HSl[(size_t)SEQ * HIDDEN];
__device__ h16   d_Wh[4][(size_t)HIDDEN * HIDDEN];
__device__ h16   d_Wl[4][(size_t)HIDDEN * HIDDEN];
__device__ h16   d_Qh[(size_t)SEQ * HIDDEN], d_Ql[(size_t)SEQ * HIDDEN];
__device__ h16   d_Kh[(size_t)SEQ * HIDDEN], d_Kl[(size_t)SEQ * HIDDEN];
__device__ h16   d_Vth[(size_t)HIDDEN * SEQ], d_Vtl[(size_t)HIDDEN * SEQ]; // per-head [d][s]
__device__ h16   d_Ph[(size_t)NHEADS * SEQ * SEQ];
__device__ h16   d_AOh[(size_t)SEQ * HIDDEN], d_AOl[(size_t)SEQ * HIDDEN];
__device__ float d_HH[NHEADS * SEQ];
__device__ int   d_keep[NHEADS * CACHE];
__device__ float d_invf[64];

// ---------------- helpers ----------------
__device__ __forceinline__ uint32_t smem_u32(const void* p) {
    uint32_t a;
    asm("{ .reg .u64 t; cvta.to.shared.u64 t, %1; cvt.u32.u64 %0, t; }" : "=r"(a) : "l"(p));
    return a;
}
__device__ __forceinline__ uint32_t sw64(uint32_t off) { return off ^ ((off >> 3) & 0x30); }

#define LDSM4(R, A) \
    asm volatile("ldmatrix.sync.aligned.m8n8.x4.shared.b16 {%0,%1,%2,%3}, [%4];" \
                 : "=r"((R)[0]), "=r"((R)[1]), "=r"((R)[2]), "=r"((R)[3]) : "r"(A))

#define MMA16816(C, A, B) \
    asm volatile("mma.sync.aligned.m16n8k16.row.col.f32.f16.f16.f32 " \
                 "{%0,%1,%2,%3},{%4,%5,%6,%7},{%8,%9},{%0,%1,%2,%3};" \
                 : "+f"((C)[0]), "+f"((C)[1]), "+f"((C)[2]), "+f"((C)[3]) \
                 : "r"((A)[0]), "r"((A)[1]), "r"((A)[2]), "r"((A)[3]), \
                   "r"((B)[0]), "r"((B)[1]))

// fp16-accumulate MMA (2x rate) for lo-magnitude cross terms
#define MMA16816H(C, A, B) \
    asm volatile("mma.sync.aligned.m16n8k16.row.col.f16.f16.f16.f16 " \
                 "{%0,%1},{%2,%3,%4,%5},{%6,%7},{%0,%1};" \
                 : "+r"((C)[0]), "+r"((C)[1]) \
                 : "r"((A)[0]), "r"((A)[1]), "r"((A)[2]), "r"((A)[3]), \
                   "r"((B)[0]), "r"((B)[1]))

#define CP16(DST, SRC) \
    asm volatile("cp.async.cg.shared.global [%0], [%1], 16;" :: "r"(DST), "l"(SRC) : "memory")
#define CP_COMMIT() asm volatile("cp.async.commit_group;" ::: "memory")
#define CP_WAIT2()  asm volatile("cp.async.wait_group 2;" ::: "memory")

// ============================================================
// Split-fp16 HMMA GEMM:  C[m,n] = alpha * sum_k A[m,k]*B[n,k]
// DROP: 0 = 3-term, 1 = drop B-lo, 2 = drop A-lo
// F16X: cross terms accumulate in fp16 (2x MMA rate)
// mode: 0 normal, 1 causal-skip n0>m0, 2 causal K-limit (PV)
// outmode: 0 = fp32 C, 1 = fp16 hi/lo pair (Chi, Clo)
// ============================================================
#define BM 128
#define BN 128
#define BK 32
#define TILEB 8192            // one operand tile: 128*32 halfs
#define STGB  (4 * TILEB)     // 32 KB/stage
#define NSTAGE 3
#define GSMEM (NSTAGE * STGB) // 96 KB

template<int DROP, bool F16X>
__global__ __launch_bounds__(256, 2) void gemm_hsplit(
    const h16* __restrict__ Ahi, const h16* __restrict__ Alo,
    const h16* __restrict__ Bhi, const h16* __restrict__ Blo,
    float* __restrict__ C, h16* __restrict__ Chi, h16* __restrict__ Clo,
    int K, int lda, int ldb, int ldc,
    long long sAz, long long sBz, long long sCz,
    float alpha, int mode, int outmode)
{
    const int m0 = blockIdx.y * BM;
    const int n0 = blockIdx.x * BN;
    if (mode == 1 && n0 > m0) return;
    Ahi += (size_t)blockIdx.z * sAz; Alo += (size_t)blockIdx.z * sAz;
    Bhi += (size_t)blockIdx.z * sBz; Blo += (size_t)blockIdx.z * sBz;

    extern __shared__ char smem[];
    const uint32_t sb = smem_u32(smem);
    const int tid = threadIdx.x;
    const int lane = tid & 31;
    const int wid = tid >> 5;
    const int wm = (wid >> 2) * 64;       // warp m offset (0 / 64)
    const int wn = (wid & 3) * 32;        // warp n offset (0/32/64/96)

    int nch = K / BK;
    if (mode == 2) { int lim = (m0 >> 5) + 4; if (lim < nch) nch = lim; }

    const h16* pAh = Ahi + (size_t)m0 * lda;
    const h16* pAl = Alo + (size_t)m0 * lda;
    const h16* pBh = Bhi + (size_t)n0 * ldb;
    const h16* pBl = Blo + (size_t)n0 * ldb;

#define LOAD_STAGE(I)                                                        \
    {                                                                        \
        const int k0_ = (I) * BK;                                            \
        const uint32_t base_ = sb + ((I) % NSTAGE) * STGB;                   \
        _Pragma("unroll")                                                    \
        for (int hh = 0; hh < 2; hh++) {                                     \
            int idx = tid + hh * 256;                                        \
            int row = idx >> 2, ch = idx & 3;                                \
            uint32_t so = sw64((uint32_t)(row * 64 + ch * 16));              \
            CP16(base_ + 0 * TILEB + so, pAh + (size_t)row * lda + k0_ + ch * 8); \
            if (DROP != 2)                                                   \
                CP16(base_ + 1 * TILEB + so, pAl + (size_t)row * lda + k0_ + ch * 8); \
            CP16(base_ + 2 * TILEB + so, pBh + (size_t)row * ldb + k0_ + ch * 8); \
            if (DROP != 1)                                                   \
                CP16(base_ + 3 * TILEB + so, pBl + (size_t)row * ldb + k0_ + ch * 8); \
        }                                                                    \
        CP_COMMIT();                                                         \
    }

    float acc[4][4][4];
#pragma unroll
    for (int i = 0; i < 4; i++)
#pragma unroll
        for (int j = 0; j < 4; j++)
#pragma unroll
            for (int e = 0; e < 4; e++) acc[i][j][e] = 0.f;
    uint32_t acc16[4][4][2];
    if (F16X) {
#pragma unroll
        for (int i = 0; i < 4; i++)
#pragma unroll
            for (int j = 0; j < 4; j++) { acc16[i][j][0] = 0u; acc16[i][j][1] = 0u; }
    }

    LOAD_STAGE(0)
    LOAD_STAGE(1)
    LOAD_STAGE(2)

    // per-lane ldmatrix row/chunk components
    const int rA = wm + (lane & 15);            // A row within CTA tile
    const int cA = lane >> 4;                   // extra k-chunk bit
    const int rB = wn + ((lane >> 4) & 1) * 8 + (lane & 7);
    const int cB = (lane >> 3) & 1;

    for (int it = 0; it < nch; it++) {
        CP_WAIT2();
        __syncthreads();
        const uint32_t base = sb + (it % NSTAGE) * STGB;
        const uint32_t aHiB = base, aLoB = base + TILEB;
        const uint32_t bHiB = base + 2 * TILEB, bLoB = base + 3 * TILEB;
#pragma unroll
        for (int ks = 0; ks < 2; ks++) {
            uint32_t bh[4][2], bl[4][2];
            const int chB = ks * 2 + cB;
#pragma unroll
            for (int p = 0; p < 2; p++) {
                uint32_t off = sw64((uint32_t)((rB + p * 16) * 64 + chB * 16));
                uint32_t r[4];
                LDSM4(r, bHiB + off);
                bh[2 * p][0] = r[0]; bh[2 * p][1] = r[1];
                bh[2 * p + 1][0] = r[2]; bh[2 * p + 1][1] = r[3];
                if (DROP != 1) {
                    LDSM4(r, bLoB + off);
                    bl[2 * p][0] = r[0]; bl[2 * p][1] = r[1];
                    bl[2 * p + 1][0] = r[2]; bl[2 * p + 1][1] = r[3];
                }
            }
            const int chA = ks * 2 + cA;
#pragma unroll
            for (int i = 0; i < 4; i++) {
                uint32_t off = sw64((uint32_t)((rA + i * 16) * 64 + chA * 16));
                uint32_t ah[4], al[4];
                LDSM4(ah, aHiB + off);
                if (DROP != 2) LDSM4(al, aLoB + off);
#pragma unroll
                for (int j = 0; j < 4; j++) {
                    MMA16816(acc[i][j], ah, bh[j]);
                    if (DROP != 1) {
                        if (F16X) MMA16816H(acc16[i][j], ah, bl[j]);
                        else      MMA16816(acc[i][j], ah, bl[j]);
                    }
                    if (DROP != 2) {
                        if (F16X) MMA16816H(acc16[i][j], al, bh[j]);
                        else      MMA16816(acc[i][j], al, bh[j]);
                    }
                }
            }
        }
        __syncthreads();
        if (it + NSTAGE < nch) { LOAD_STAGE(it + NSTAGE) } else { CP_COMMIT(); }
    }
#undef LOAD_STAGE

    // fold fp16 cross accumulators into fp32
    if (F16X) {
#pragma unroll
        for (int i = 0; i < 4; i++)
#pragma unroll
            for (int j = 0; j < 4; j++) {
                h162 x0 = *(h162*)&acc16[i][j][0];
                h162 x1 = *(h162*)&acc16[i][j][1];
                acc[i][j][0] += __half2float(x0.x);
                acc[i][j][1] += __half2float(x0.y);
                acc[i][j][2] += __half2float(x1.x);
                acc[i][j][3] += __half2float(x1.y);
            }
    }

    // epilogue
    const int gr = lane >> 2;
    const int gc = (lane & 3) * 2;
    if (outmode == 0) {
        float* Cb = C + (size_t)blockIdx.z * sCz;
#pragma unroll
        for (int i = 0; i < 4; i++) {
#pragma unroll
            for (int j = 0; j < 4; j++) {
                int row = m0 + wm + i * 16 + gr;
                int col = n0 + wn + j * 8 + gc;
                float2 v0 = { acc[i][j][0] * alpha, acc[i][j][1] * alpha };
                float2 v1 = { acc[i][j][2] * alpha, acc[i][j][3] * alpha };
                *(float2*)(Cb + (size_t)row * ldc + col) = v0;
                *(float2*)(Cb + (size_t)(row + 8) * ldc + col) = v1;
            }
        }
    } else {
        h16* Ch = Chi + (size_t)blockIdx.z * sCz;
        h16* Cl = Clo + (size_t)blockIdx.z * sCz;
#pragma unroll
        for (int i = 0; i < 4; i++) {
#pragma unroll
            for (int j = 0; j < 4; j++) {
                int row = m0 + wm + i * 16 + gr;
                int col = n0 + wn + j * 8 + gc;
#pragma unroll
                for (int half = 0; half < 2; half++) {
                    float e0 = acc[i][j][2 * half] * alpha;
                    float e1 = acc[i][j][2 * half + 1] * alpha;
                    h162 H; H.x = __float2half_rn(e0); H.y = __float2half_rn(e1);
                    h162 L;
                    L.x = __float2half_rn(e0 - __half2float(H.x));
                    L.y = __float2half_rn(e1 - __half2float(H.y));
                    size_t idx = (size_t)(row + half * 8) * ldc + col;
                    *(h162*)(Ch + idx) = H;
                    *(h162*)(Cl + idx) = L;
                }
            }
        }
    }
}

// ============================================================
// elementwise: fp32 -> fp16 hi/lo split
// ============================================================
__global__ void split_kernel(const float* __restrict__ src, h16* __restrict__ hi,
                             h16* __restrict__ lo, int n4)
{
    int i = blockIdx.x * blockDim.x + threadIdx.x;
    if (i >= n4) return;
    float4 v = ((const float4*)src)[i];
    h16 h0 = __float2half_rn(v.x), h1 = __float2half_rn(v.y);
    h16 h2 = __float2half_rn(v.z), h3 = __float2half_rn(v.w);
    h162 H0; H0.x = h0; H0.y = h1;
    h162 H1; H1.x = h2; H1.y = h3;
    ((h162*)hi)[2 * i] = H0; ((h162*)hi)[2 * i + 1] = H1;
    h162 L0, L1;
    L0.x = __float2half_rn(v.x - __half2float(h0));
    L0.y = __float2half_rn(v.y - __half2float(h1));
    L1.x = __float2half_rn(v.z - __half2float(h2));
    L1.y = __float2half_rn(v.w - __half2float(h3));
    ((h162*)lo)[2 * i] = L0; ((h162*)lo)[2 * i + 1] = L1;
}

__global__ void invf_kernel()
{
    int j = threadIdx.x;   // 64
    d_invf[j] = (float)exp(-(double)j * (log(10000.0) / 64.0));
}

// ============================================================
// RoPE on Q,K (fp32 in-place) + fused hi/lo split. grid(SEQ), 512 thr.
// ============================================================
__device__ __forceinline__ void st_hl(h16* hi, h16* lo, size_t idx, float a, float b)
{
    h162 H; H.x = __float2half_rn(a); H.y = __float2half_rn(b);
    *(h162*)(hi + idx) = H;
    h162 L;
    L.x = __float2half_rn(a - __half2float(H.x));
    L.y = __float2half_rn(b - __half2float(H.y));
    *(h162*)(lo + idx) = L;
}

__global__ __launch_bounds__(512) void rope_split_kernel(const int* __restrict__ pos_ids)
{
    int s = blockIdx.x;
    int t = threadIdx.x;
    int h = t >> 4;
    int j = (t & 15) << 2;
    float pos = (float)pos_ids[s];
    size_t base = (size_t)s * HIDDEN + (size_t)h * HDIM;
    float4 q0 = *(float4*)(d_Q + base + j);
    float4 q1 = *(float4*)(d_Q + base + 64 + j);
    float4 k0 = *(float4*)(d_K + base + j);
    float4 k1 = *(float4*)(d_K + base + 64 + j);
    float cc[4], ss[4];
#pragma unroll
    for (int e = 0; e < 4; e++) {
        float ang = pos * d_invf[j + e];
        sincosf(ang, &ss[e], &cc[e]);
    }
    float4 Q0, Q1, K0, K1;
    Q0.x = q0.x * cc[0] - q1.x * ss[0];  Q1.x = q1.x * cc[0] + q0.x * ss[0];
    Q0.y = q0.y * cc[1] - q1.y * ss[1];  Q1.y = q1.y * cc[1] + q0.y * ss[1];
    Q0.z = q0.z * cc[2] - q1.z * ss[2];  Q1.z = q1.z * cc[2] + q0.z * ss[2];
    Q0.w = q0.w * cc[3] - q1.w * ss[3];  Q1.w = q1.w * cc[3] + q0.w * ss[3];
    K0.x = k0.x * cc[0] - k1.x * ss[0];  K1.x = k1.x * cc[0] + k0.x * ss[0];
    K0.y = k0.y * cc[1] - k1.y * ss[1];  K1.y = k1.y * cc[1] + k0.y * ss[1];
    K0.z = k0.z * cc[2] - k1.z * ss[2];  K1.z = k1.z * cc[2] + k0.z * ss[2];
    K0.w = k0.w * cc[3] - k1.w * ss[3];  K1.w = k1.w * cc[3] + k0.w * ss[3];
    *(float4*)(d_Q + base + j) = Q0;      *(float4*)(d_Q + base + 64 + j) = Q1;
    *(float4*)(d_K + base + j) = K0;      *(float4*)(d_K + base + 64 + j) = K1;
    st_hl(d_Qh, d_Ql, base + j, Q0.x, Q0.y);       st_hl(d_Qh, d_Ql, base + j + 2, Q0.z, Q0.w);
    st_hl(d_Qh, d_Ql, base + 64 + j, Q1.x, Q1.y);  st_hl(d_Qh, d_Ql, base + 64 + j + 2, Q1.z, Q1.w);
    st_hl(d_Kh, d_Kl, base + j, K0.x, K0.y);       st_hl(d_Kh, d_Kl, base + j + 2, K0.z, K0.w);
    st_hl(d_Kh, d_Kl, base + 64 + j, K1.x, K1.y);  st_hl(d_Kh, d_Kl, base + 64 + j + 2, K1.z, K1.w);
}

// ============================================================
// V transpose + split: Vt[h][d][s] = V[s][h*128+d]. grid(64,4,32), block(32,8)
// ============================================================
__global__ void vtrans_kernel()
{
    __shared__ float tile[32][33];
    int h = blockIdx.z;
    int s0 = blockIdx.x * 32;
    int d0 = blockIdx.y * 32;
    for (int r = threadIdx.y; r < 32; r += 8)
        tile[r][threadIdx.x] = d_V[(size_t)(s0 + r) * HIDDEN + h * HDIM + d0 + threadIdx.x];
    __syncthreads();
    for (int r = threadIdx.y; r < 32; r += 8) {
        float x = tile[threadIdx.x][r];
        size_t idx = ((size_t)h * HDIM + d0 + r) * SEQ + s0 + threadIdx.x;
        h16 hi = __float2half_rn(x);
        d_Vth[idx] = hi;
        d_Vtl[idx] = __float2half_rn(x - __half2float(hi));
    }
}

// ============================================================
// causal softmax: read d_S row, write Ph (values k<=q only);
// zero Ph band (q, tile_end) so PV's K-limited reads see zeros.
// grid(SEQ, NHEADS), 256 thr.
// ============================================================
__global__ __launch_bounds__(256) void softmax_kernel()
{
    __shared__ float red[256];
    __shared__ float ebuf[SEQ];
    int q = blockIdx.x, h = blockIdx.y;
    const float* srow = d_S + ((size_t)h * SEQ + q) * SEQ;
    h16* ph = d_Ph + ((size_t)h * SEQ + q) * SEQ;
    int n = q + 1;
    int tid = threadIdx.x;
    float mx = -FLT_MAX;
    for (int k = tid; k < n; k += 256) mx = fmaxf(mx, srow[k]);
    red[tid] = mx; __syncthreads();
    for (int o = 128; o > 0; o >>= 1) { if (tid < o) red[tid] = fmaxf(red[tid], red[tid + o]); __syncthreads(); }
    mx = red[0]; __syncthreads();
    float sum = 0.f;
    for (int k = tid; k < n; k += 256) { float e = __expf(srow[k] - mx); ebuf[k] = e; sum += e; }
    red[tid] = sum; __syncthreads();
    for (int o = 128; o > 0; o >>= 1) { if (tid < o) red[tid] += red[tid + o]; __syncthreads(); }
    float inv = 1.f / red[0];
    __syncthreads();
    int npair = n >> 1;
    for (int i = tid; i < npair; i += 256) {
        float e0 = ebuf[2 * i] * inv, e1 = ebuf[2 * i + 1] * inv;
        h162 H; H.x = __float2half_rn(e0); H.y = __float2half_rn(e1);
        *(h162*)(ph + 2 * i) = H;
    }
    if ((n & 1) && tid == 0)
        ph[n - 1] = __float2half_rn(ebuf[n - 1] * inv);
    int tileEnd = ((q >> 7) + 1) << 7;
    h16 z = __float2half_rn(0.f);
    for (int k = n + tid; k < tileEnd; k += 256) ph[k] = z;
}

// ============================================================
// hh_score[h,k] = sum_{q>=k} Ph[h,q,k]. grid(8, NHEADS), 256 thr.
// ============================================================
__global__ void colsum_kernel()
{
    int h = blockIdx.y;
    int k = blockIdx.x * 256 + threadIdx.x;
    const h16* bh = d_Ph + (size_t)h * SEQ * SEQ + k;
    float s = 0.f;
    int q = k;
    for (; q & 3; q++)
        s += __half2float(bh[(size_t)q * SEQ]);
    float s0 = 0.f, s1 = 0.f, s2 = 0.f, s3 = 0.f;
    for (; q < SEQ; q += 4) {
        s0 += __half2float(bh[(size_t)q * SEQ]);
        s1 += __half2float(bh[(size_t)(q + 1) * SEQ]);
        s2 += __half2float(bh[(size_t)(q + 2) * SEQ]);
        s3 += __half2float(bh[(size_t)(q + 3) * SEQ]);
    }
    d_HH[h * SEQ + k] = s + (s0 + s1) + (s2 + s3);
}

// ============================================================
// top-256 per head + sort
// ============================================================
__global__ __launch_bounds__(1024) void topk_kernel()
{
    __shared__ float sv[2048];
    __shared__ int   si[2048];
    __shared__ int   tki[256];
    int h = blockIdx.x, tid = threadIdx.x;
    for (int i = tid; i < 2048; i += 1024) {
        sv[i] = (i < SEL) ? d_HH[h * SEQ + i] : -FLT_MAX;
        si[i] = i;
    }
    __syncthreads();
    for (int k = 2; k <= 2048; k <<= 1) {
        for (int j = k >> 1; j > 0; j >>= 1) {
            for (int i = tid; i < 2048; i += 1024) {
                int l = i ^ j;
                if (l > i) {
                    float vi = sv[i], vl = sv[l];
                    int ii = si[i], il = si[l];
                    bool up = ((i & k) == 0);
                    bool bli = (vl > vi) || (vl == vi && il < ii);
                    bool bil = (vi > vl) || (vi == vl && ii < il);
                    if (up ? bli : bil) { sv[i] = vl; sv[l] = vi; si[i] = il; si[l] = ii; }
                }
            }
            __syncthreads();
        }
    }
    if (tid < 256) tki[tid] = si[tid];
    __syncthreads();
    for (int k = 2; k <= 256; k <<= 1) {
        for (int j = k >> 1; j > 0; j >>= 1) {
            if (tid < 256) {
                int i = tid, l = i ^ j;
                if (l > i) {
                    int a = tki[i], b = tki[l];
                    bool up = ((i & k) == 0);
                    if (up ? (a > b) : (a < b)) { tki[i] = b; tki[l] = a; }
                }
            }
            __syncthreads();
        }
    }
    for (int i = tid; i < CACHE; i += 1024)
        d_keep[h * CACHE + i] = (i < HHK) ? tki[i] : (SEL + (i - HHK));
}

__global__ void gather_kernel(float* __restrict__ out)
{
    int h = blockIdx.y, j = blockIdx.x, d = threadIdx.x;
    int s = d_keep[h * CACHE + j];
    size_t dst = (size_t)8388608 + ((size_t)h * CACHE + j) * HDIM + d;
    size_t src = (size_t)s * HIDDEN + (size_t)h * HDIM + d;
    out[dst] = d_K[src];
    out[dst + 3145728] = d_V[src];
    if (d == 0) out[(size_t)14680064 + h * CACHE + j] = d_HH[h * SEQ + s];
}

// ============================================================
extern "C" void kernel_launch(void* const* d_in, const int* in_sizes, int n_in,
                              void* d_out, int out_size)
{
    const float* hs  = (const float*)d_in[0];
    const int*   pos = (const int*)d_in[1];
    const float* W[4] = { (const float*)d_in[2], (const float*)d_in[3],
                          (const float*)d_in[4], (const float*)d_in[5] };
    float* out = (float*)d_out;

    cudaFuncSetAttribute(gemm_hsplit<0, true>,  cudaFuncAttributeMaxDynamicSharedMemorySize, GSMEM);
    cudaFuncSetAttribute(gemm_hsplit<1, false>, cudaFuncAttributeMaxDynamicSharedMemorySize, GSMEM);
    cudaFuncSetAttribute(gemm_hsplit<2, false>, cudaFuncAttributeMaxDynamicSharedMemorySize, GSMEM);

    float *Qp, *Kp, *Vp, *Sp;
    h16 *HSh, *HSl, *Whp[4], *Wlp[4], *Qhp, *Qlp, *Khp, *Klp, *Vthp, *Vtlp, *Php, *AOhp, *AOlp;
    cudaGetSymbolAddress((void**)&Qp, d_Q);   cudaGetSymbolAddress((void**)&Kp, d_K);
    cudaGetSymbolAddress((void**)&Vp, d_V);
    cudaGetSymbolAddress((void**)&Sp, d_S);
    cudaGetSymbolAddress((void**)&HSh, d_HSh); cudaGetSymbolAddress((void**)&HSl, d_HSl);
    {
        h16 *wh, *wl;
        cudaGetSymbolAddress((void**)&wh, d_Wh); cudaGetSymbolAddress((void**)&wl, d_Wl);
        for (int i = 0; i < 4; i++) { Whp[i] = wh + (size_t)i * HIDDEN * HIDDEN; Wlp[i] = wl + (size_t)i * HIDDEN * HIDDEN; }
    }
    cudaGetSymbolAddress((void**)&Qhp, d_Qh); cudaGetSymbolAddress((void**)&Qlp, d_Ql);
    cudaGetSymbolAddress((void**)&Khp, d_Kh); cudaGetSymbolAddress((void**)&Klp, d_Kl);
    cudaGetSymbolAddress((void**)&Vthp, d_Vth); cudaGetSymbolAddress((void**)&Vtlp, d_Vtl);
    cudaGetSymbolAddress((void**)&Php, d_Ph);
    cudaGetSymbolAddress((void**)&AOhp, d_AOh); cudaGetSymbolAddress((void**)&AOlp, d_AOl);

    const float inv_sqrt_d = 0.08838834764831843f;

    // ncu -s 5 -c 1 captures launch index 5 => Q projection GEMM
    invf_kernel<<<1, 64>>>();                                                                    // 0
    split_kernel<<<(SEQ * HIDDEN / 4 + 255) / 256, 256>>>(hs, HSh, HSl, SEQ * HIDDEN / 4);       // 1
    split_kernel<<<(HIDDEN * HIDDEN / 4 + 255) / 256, 256>>>(W[0], Whp[0], Wlp[0], HIDDEN * HIDDEN / 4); // 2
    split_kernel<<<(HIDDEN * HIDDEN / 4 + 255) / 256, 256>>>(W[1], Whp[1], Wlp[1], HIDDEN * HIDDEN / 4); // 3
    split_kernel<<<(HIDDEN * HIDDEN / 4 + 255) / 256, 256>>>(W[2], Whp[2], Wlp[2], HIDDEN * HIDDEN / 4); // 4

    // Q projection (3-term, f16 cross-acc) — profiled launch (index 5)
    gemm_hsplit<0, true><<<dim3(32, 16, 1), 256, GSMEM>>>(HSh, HSl, Whp[0], Wlp[0], Qp, 0, 0,    // 5
        HIDDEN, HIDDEN, HIDDEN, HIDDEN, 0, 0, 0, 1.f, 0, 0);
    // K projection (3-term, f16 cross-acc)
    gemm_hsplit<0, true><<<dim3(32, 16, 1), 256, GSMEM>>>(HSh, HSl, Whp[1], Wlp[1], Kp, 0, 0,
        HIDDEN, HIDDEN, HIDDEN, HIDDEN, 0, 0, 0, 1.f, 0, 0);
    // V projection (2-term)
    gemm_hsplit<1, false><<<dim3(32, 16, 1), 256, GSMEM>>>(HSh, HSl, Whp[2], Wlp[2], Vp, 0, 0,
        HIDDEN, HIDDEN, HIDDEN, HIDDEN, 0, 0, 0, 1.f, 0, 0);

    split_kernel<<<(HIDDEN * HIDDEN / 4 + 255) / 256, 256>>>(W[3], Whp[3], Wlp[3], HIDDEN * HIDDEN / 4);

    rope_split_kernel<<<SEQ, 512>>>(pos);
    vtrans_kernel<<<dim3(SEQ / 32, HDIM / 32, NHEADS), dim3(32, 8)>>>();

    // scores: S[h] = (Q_h @ K_h^T)/sqrt(d)  (3-term f16 cross-acc, causal tile skip)
    gemm_hsplit<0, true><<<dim3(16, 16, NHEADS), 256, GSMEM>>>(Qhp, Qlp, Khp, Klp, Sp, 0, 0,
        HDIM, HIDDEN, HIDDEN, SEQ, HDIM, HDIM, (long long)SEQ * SEQ, inv_sqrt_d, 1, 0);

    softmax_kernel<<<dim3(SEQ, NHEADS), 256>>>();
    colsum_kernel<<<dim3(8, NHEADS), 256>>>();

    // AO_h = P[h] @ V_h  (2-term: Ph only; causal K limit; emit hi/lo directly)
    gemm_hsplit<2, false><<<dim3(1, 16, NHEADS), 256, GSMEM>>>(Php, Php, Vthp, Vtlp, 0, AOhp, AOlp,
        SEQ, SEQ, SEQ, HIDDEN, (long long)SEQ * SEQ, (long long)HDIM * SEQ, HDIM, 1.f, 2, 1);

    // out = AO @ Wo^T  (2-term, fp32 out)
    gemm_hsplit<1, false><<<dim3(32, 16, 1), 256, GSMEM>>>(AOhp, AOlp, Whp[3], Wlp[3], out, 0, 0,
        HIDDEN, HIDDEN, HIDDEN, HIDDEN, 0, 0, 0, 1.f, 0, 0);

    topk_kernel<<<NHEADS, 1024>>>();
    gather_kernel<<<dim3(CACHE, NHEADS), 128>>>(out);
}